// round 3
// baseline (speedup 1.0000x reference)
#include <cuda_runtime.h>

// LayerNorm-LSTM critic. N=2048 chains x T=256 steps, HID=64, D=128 (96 obs + 32 act).
// 128 blocks x 256 threads; block owns 16 rows for all timesteps; W resident in SMEM.
// fp32 math with packed fma.rn.f32x2 (FFMA2) for 2x fp32 FMA throughput on sm_103a.

#define TSTEPS 256
#define NROWS  16
#define XP     132   // xbuf row pitch (floats): 16B-aligned rows, 2-way bank conflict max
#define HP     68    // hbuf row pitch

// shared memory layout (bytes)
#define SM_W     0
#define SM_XBUF  (192*256*4)                      // 196608
#define SM_HBUF  (SM_XBUF + 2*NROWS*XP*4)         // +16896
#define SM_P1    (SM_HBUF + NROWS*HP*4)           // +4352
#define SM_P2    (SM_P1 + NROWS*16*8*4)           // +8192
#define SM_P3    (SM_P2 + NROWS*16*2*4)           // +2048
#define SM_S1    (SM_P3 + NROWS*16*4)             // +1024
#define SM_S2    (SM_S1 + NROWS*4*2*4)            // +512
#define SM_TOTAL (SM_S2 + NROWS*2*4)              // +128  => 229760 B total

__device__ __forceinline__ unsigned long long pack2(float x, float y) {
  unsigned long long r;
  asm("mov.b64 %0, {%1, %2};" : "=l"(r) : "f"(x), "f"(y));
  return r;
}
__device__ __forceinline__ float2 unpack2(unsigned long long v) {
  float2 f;
  asm("mov.b64 {%0, %1}, %2;" : "=f"(f.x), "=f"(f.y) : "l"(v));
  return f;
}
#define FMA2(d, a, b) asm("fma.rn.f32x2 %0, %1, %2, %0;" : "+l"(d) : "l"(a), "l"(b))

__device__ __forceinline__ float sigm(float x) {
  return __fdividef(1.f, 1.f + __expf(-x));
}
__device__ __forceinline__ float tanhx(float x) {
  float xx = fminf(fmaxf(x, -15.f), 15.f);
  float e = __expf(2.f * xx);
  return __fdividef(e - 1.f, e + 1.f);
}

// Stage x_t (obs||act) for this block's 16 rows into smem via cp.async (512 x 16B chunks).
__device__ __forceinline__ void load_x_async(const float* __restrict__ obss,
                                             const float* __restrict__ acts,
                                             float* dst, int n0, int t, int tid) {
#pragma unroll
  for (int it = 0; it < 2; it++) {
    int cidx = tid + it * 256;
    int row = cidx >> 5;      // 0..15
    int ch  = cidx & 31;      // 0..31 (24 obs chunks + 8 act chunks)
    const float* src;
    int col;
    if (ch < 24) { src = obss + ((size_t)(n0 + row) * TSTEPS + t) * 96 + ch * 4;        col = ch * 4; }
    else         { src = acts + ((size_t)(n0 + row) * TSTEPS + t) * 32 + (ch - 24) * 4; col = 96 + (ch - 24) * 4; }
    unsigned int da = (unsigned int)__cvta_generic_to_shared(dst + row * XP + col);
    asm volatile("cp.async.ca.shared.global [%0], [%1], 16;" :: "r"(da), "l"(src));
  }
}

__global__ void __launch_bounds__(256, 1)
critic_lnlstm_kernel(const float* __restrict__ obss, const float* __restrict__ acts,
                     const float* __restrict__ Wg,   const float* __restrict__ gamma,
                     const float* __restrict__ beta, const float* __restrict__ dW,
                     const float* __restrict__ db,   float* __restrict__ out) {
  extern __shared__ char smem[];
  float* Wsh  = (float*)(smem + SM_W);
  float* xbuf = (float*)(smem + SM_XBUF);
  float* hbuf = (float*)(smem + SM_HBUF);
  float* P1   = (float*)(smem + SM_P1);
  float* P2   = (float*)(smem + SM_P2);
  float* P3   = (float*)(smem + SM_P3);
  float* S1   = (float*)(smem + SM_S1);
  float* S2   = (float*)(smem + SM_S2);

  const int tid = threadIdx.x;
  const int r = tid & 15;        // row within block
  const int q = tid >> 4;        // colgroup: owns cols {4q..4q+3} of each gate
  const int n0 = blockIdx.x * NROWS;

  // Stage W [192][256] into SMEM
  {
    const float4* s4 = (const float4*)Wg;
    float4* d4 = (float4*)Wsh;
    for (int i = tid; i < 192 * 256 / 4; i += 256) d4[i] = s4[i];
  }
  for (int i = tid; i < NROWS * HP; i += 256) hbuf[i] = 0.f;   // h0 = 0

  // Preload x_0
  load_x_async(obss, acts, xbuf, n0, 0, tid);
  asm volatile("cp.async.commit_group;");

  // Loop-invariant per-thread constants (registers; occupancy is smem-bound anyway)
  float gam[5][4], bet[5][4], dwr[4];
#pragma unroll
  for (int g = 0; g < 5; g++) {
    float4 gv = *(const float4*)(gamma + g * 64 + 4 * q);
    float4 bv = *(const float4*)(beta  + g * 64 + 4 * q);
    gam[g][0] = gv.x; gam[g][1] = gv.y; gam[g][2] = gv.z; gam[g][3] = gv.w;
    bet[g][0] = bv.x; bet[g][1] = bv.y; bet[g][2] = bv.z; bet[g][3] = bv.w;
  }
  {
    float4 dv = *(const float4*)(dW + 4 * q);
    dwr[0] = dv.x; dwr[1] = dv.y; dwr[2] = dv.z; dwr[3] = dv.w;
  }
  const float dbr = db[0];

  float cstate[4] = {0.f, 0.f, 0.f, 0.f};   // carried c (post-LN) for positions 4q..4q+3

  asm volatile("cp.async.wait_group 0;");
  __syncthreads();

  for (int t = 0; t < TSTEPS; t++) {
    const int cur = t & 1;
    if (t + 1 < TSTEPS) load_x_async(obss, acts, xbuf + (cur ^ 1) * NROWS * XP, n0, t + 1, tid);
    asm volatile("cp.async.commit_group;");

    // ---- GEMM: z[r][4q..4q+3 per gate] = [x_t, h] @ W (f32x2 packed) ----
    unsigned long long acc[8];
#pragma unroll
    for (int i = 0; i < 8; i++) acc[i] = 0ull;

    {
      const float* xrow = xbuf + cur * NROWS * XP + r * XP;
      const float* wb   = Wsh + q * 4;
#pragma unroll 2
      for (int k = 0; k < 128; k += 4) {
        float4 xv = *(const float4*)(xrow + k);
#pragma unroll
        for (int kk = 0; kk < 4; kk++) {
          float xs = (kk == 0) ? xv.x : (kk == 1) ? xv.y : (kk == 2) ? xv.z : xv.w;
          unsigned long long xx = pack2(xs, xs);
          const float* wr = wb + (k + kk) * 256;
#pragma unroll
          for (int g = 0; g < 4; g++) {
            ulonglong2 w = *(const ulonglong2*)(wr + g * 64);
            FMA2(acc[2 * g],     xx, w.x);
            FMA2(acc[2 * g + 1], xx, w.y);
          }
        }
      }
      const float* hrow = hbuf + r * HP;
      const float* wbh  = wb + 128 * 256;
#pragma unroll 2
      for (int k = 0; k < 64; k += 4) {
        float4 hv = *(const float4*)(hrow + k);
#pragma unroll
        for (int kk = 0; kk < 4; kk++) {
          float hs = (kk == 0) ? hv.x : (kk == 1) ? hv.y : (kk == 2) ? hv.z : hv.w;
          unsigned long long xx = pack2(hs, hs);
          const float* wr = wbh + (k + kk) * 256;
#pragma unroll
          for (int g = 0; g < 4; g++) {
            ulonglong2 w = *(const ulonglong2*)(wr + g * 64);
            FMA2(acc[2 * g],     xx, w.x);
            FMA2(acc[2 * g + 1], xx, w.y);
          }
        }
      }
    }

    float z[4][4];
#pragma unroll
    for (int g = 0; g < 4; g++) {
      float2 a = unpack2(acc[2 * g]);
      float2 b = unpack2(acc[2 * g + 1]);
      z[g][0] = a.x; z[g][1] = a.y; z[g][2] = b.x; z[g][3] = b.y;
    }

    // ---- Gate layernorm stats (per row, per gate, over 64 = 16 threads x 4) ----
#pragma unroll
    for (int g = 0; g < 4; g++) {
      float s  = z[g][0] + z[g][1] + z[g][2] + z[g][3];
      float ss = z[g][0] * z[g][0] + z[g][1] * z[g][1] + z[g][2] * z[g][2] + z[g][3] * z[g][3];
      P1[(r * 16 + q) * 8 + 2 * g]     = s;
      P1[(r * 16 + q) * 8 + 2 * g + 1] = ss;
    }
    __syncthreads();
    if (tid < 64) {                       // thread (g=q, r) reduces gate g of row r
      const int g = q;
      const float* base = P1 + r * 16 * 8 + 2 * g;
      float s = 0.f, ss = 0.f;
#pragma unroll
      for (int qq = 0; qq < 16; qq++) { s += base[qq * 8]; ss += base[qq * 8 + 1]; }
      float m = s * 0.015625f;
      float v = fmaxf(ss * 0.015625f - m * m, 0.f);
      float2 st; st.x = m; st.y = rsqrtf(v + 1e-12f);
      ((float2*)S1)[r * 4 + g] = st;
    }
    __syncthreads();

    // ---- Normalize gates, LSTM cell ----
    float2 sti = ((const float2*)S1)[r * 4 + 0];
    float2 stj = ((const float2*)S1)[r * 4 + 1];
    float2 stf = ((const float2*)S1)[r * 4 + 2];
    float2 sto = ((const float2*)S1)[r * 4 + 3];
    float nc[4], on[4];
    float cs = 0.f, css = 0.f;
#pragma unroll
    for (int j = 0; j < 4; j++) {
      float zi = (z[0][j] - sti.x) * sti.y * gam[0][j] + bet[0][j];
      float zj = (z[1][j] - stj.x) * stj.y * gam[1][j] + bet[1][j];
      float zf = (z[2][j] - stf.x) * stf.y * gam[2][j] + bet[2][j];
      on[j]    = (z[3][j] - sto.x) * sto.y * gam[3][j] + bet[3][j];
      float c = cstate[j] * sigm(zf + 1.f) + sigm(zi) * tanhx(zj);   // forget_bias = 1
      nc[j] = c; cs += c; css += c * c;
    }
    ((float2*)P2)[r * 16 + q] = make_float2(cs, css);
    __syncthreads();
    if (q == 0) {                          // thread (0, r) reduces c-LN stats of row r
      const float2* b2 = (const float2*)P2 + r * 16;
      float s = 0.f, ss = 0.f;
#pragma unroll
      for (int qq = 0; qq < 16; qq++) { float2 p = b2[qq]; s += p.x; ss += p.y; }
      float m = s * 0.015625f;
      float v = fmaxf(ss * 0.015625f - m * m, 0.f);
      ((float2*)S2)[r] = make_float2(m, rsqrtf(v + 1e-12f));
    }
    __syncthreads();

    // ---- c-LN, new h, per-thread q-partial ----
    float2 stc = ((const float2*)S2)[r];
    float qp = 0.f;
#pragma unroll
    for (int j = 0; j < 4; j++) {
      float cn = (nc[j] - stc.x) * stc.y * gam[4][j] + bet[4][j];
      cstate[j] = cn;                                   // carried c is post-LN
      float h = tanhx(cn) * sigm(on[j]);
      hbuf[r * HP + 4 * q + j] = h;
      qp += h * dwr[j];
    }
    P3[r * 16 + q] = qp;
    asm volatile("cp.async.wait_group 0;");             // x_{t+1} staged
    __syncthreads();                                    // h + x visible for next step
    if (q == 0) {
      const float* b3 = P3 + r * 16;
      float s = dbr;
#pragma unroll
      for (int qq = 0; qq < 16; qq++) s += b3[qq];
      out[(size_t)(n0 + r) * TSTEPS + t] = s;           // q[n][t]
    }
  }
}

extern "C" void kernel_launch(void* const* d_in, const int* in_sizes, int n_in,
                              void* d_out, int out_size) {
  const float* obss  = (const float*)d_in[0];
  const float* acts  = (const float*)d_in[1];
  const float* W     = (const float*)d_in[2];
  const float* gamma = (const float*)d_in[3];
  const float* beta  = (const float*)d_in[4];
  const float* dW    = (const float*)d_in[5];
  const float* db    = (const float*)d_in[6];
  float* out = (float*)d_out;

  cudaFuncSetAttribute(critic_lnlstm_kernel,
                       cudaFuncAttributeMaxDynamicSharedMemorySize, SM_TOTAL);
  critic_lnlstm_kernel<<<128, 256, SM_TOTAL>>>(obss, acts, W, gamma, beta, dW, db, out);
}

// round 4
// speedup vs baseline: 1.4031x; 1.4031x over previous
#include <cuda_runtime.h>

// LayerNorm-LSTM critic. N=2048 x T=256, HID=64, D=128 (96 obs + 32 act).
// 128 blocks x 256 threads; block owns 16 rows; W (192x256 f32) resident in SMEM.
// GEMM: 2 rows x 16 cols per thread, in-warp split-K (lane bit 4), f32x2 FMA,
// shfl-combine. LN/cell phase per (row = 2rp+kt, colgroup q) as previously verified.

#define TSTEPS 256
#define NROWS  16
#define XP     132   // xbuf row pitch (floats), 16B-aligned rows
#define HP     68    // hbuf row pitch

// shared memory layout (bytes)
#define SM_W     0
#define SM_XBUF  (192*256*4)                      // 196608
#define SM_HBUF  (SM_XBUF + 2*NROWS*XP*4)         // +16896
#define SM_P1    (SM_HBUF + NROWS*HP*4)           // +4352
#define SM_P2    (SM_P1 + NROWS*16*8*4)           // +8192
#define SM_P3    (SM_P2 + NROWS*16*2*4)           // +2048
#define SM_S1    (SM_P3 + NROWS*16*4)             // +1024
#define SM_S2    (SM_S1 + NROWS*4*2*4)            // +512
#define SM_TOTAL (SM_S2 + NROWS*2*4)              // +128  => 229760 B total

__device__ __forceinline__ unsigned long long pack2(float x, float y) {
  unsigned long long r;
  asm("mov.b64 %0, {%1, %2};" : "=l"(r) : "f"(x), "f"(y));
  return r;
}
__device__ __forceinline__ float2 unpack2(unsigned long long v) {
  float2 f;
  asm("mov.b64 {%0, %1}, %2;" : "=f"(f.x), "=f"(f.y) : "l"(v));
  return f;
}
#define FMA2(d, a, b) asm("fma.rn.f32x2 %0, %1, %2, %0;" : "+l"(d) : "l"(a), "l"(b))
#define ADD2(d, s)    asm("add.rn.f32x2 %0, %0, %1;" : "+l"(d) : "l"(s))

__device__ __forceinline__ float sigm(float x) {
  return __fdividef(1.f, 1.f + __expf(-x));
}
__device__ __forceinline__ float tanhx(float x) {
  float xx = fminf(fmaxf(x, -15.f), 15.f);
  float e = __expf(2.f * xx);
  return __fdividef(e - 1.f, e + 1.f);
}

// Stage x_t (obs||act) for this block's 16 rows into smem via cp.async (512 x 16B).
__device__ __forceinline__ void load_x_async(const float* __restrict__ obss,
                                             const float* __restrict__ acts,
                                             float* dst, int n0, int t, int tid) {
#pragma unroll
  for (int it = 0; it < 2; it++) {
    int cidx = tid + it * 256;
    int row = cidx >> 5;      // 0..15
    int ch  = cidx & 31;      // 24 obs chunks + 8 act chunks
    const float* src;
    int col;
    if (ch < 24) { src = obss + ((size_t)(n0 + row) * TSTEPS + t) * 96 + ch * 4;        col = ch * 4; }
    else         { src = acts + ((size_t)(n0 + row) * TSTEPS + t) * 32 + (ch - 24) * 4; col = 96 + (ch - 24) * 4; }
    unsigned int da = (unsigned int)__cvta_generic_to_shared(dst + row * XP + col);
    asm volatile("cp.async.ca.shared.global [%0], [%1], 16;" :: "r"(da), "l"(src));
  }
}

// 2-row x 16-col microkernel over NK k-values.
template<int NK>
__device__ __forceinline__ void gemm_seg(const float* __restrict__ p0,
                                         const float* __restrict__ p1,
                                         const float* __restrict__ w,
                                         unsigned long long* acc0,
                                         unsigned long long* acc1) {
#pragma unroll 2
  for (int k = 0; k < NK; k += 4) {
    float4 a4 = *(const float4*)(p0 + k);
    float4 b4 = *(const float4*)(p1 + k);
    float xa[4] = {a4.x, a4.y, a4.z, a4.w};
    float xb[4] = {b4.x, b4.y, b4.z, b4.w};
#pragma unroll
    for (int kk = 0; kk < 4; kk++) {
      unsigned long long ua = pack2(xa[kk], xa[kk]);
      unsigned long long ub = pack2(xb[kk], xb[kk]);
      const float* wr = w + (k + kk) * 256;
#pragma unroll
      for (int g = 0; g < 4; g++) {
        ulonglong2 wv = *(const ulonglong2*)(wr + g * 64);
        FMA2(acc0[2 * g],     ua, wv.x);
        FMA2(acc0[2 * g + 1], ua, wv.y);
        FMA2(acc1[2 * g],     ub, wv.x);
        FMA2(acc1[2 * g + 1], ub, wv.y);
      }
    }
  }
}

__global__ void __launch_bounds__(256, 1)
critic_lnlstm_kernel(const float* __restrict__ obss, const float* __restrict__ acts,
                     const float* __restrict__ Wg,   const float* __restrict__ gamma,
                     const float* __restrict__ beta, const float* __restrict__ dW,
                     const float* __restrict__ db,   float* __restrict__ out) {
  extern __shared__ char smem[];
  float* Wsh  = (float*)(smem + SM_W);
  float* xbuf = (float*)(smem + SM_XBUF);
  float* hbuf = (float*)(smem + SM_HBUF);
  float* P1   = (float*)(smem + SM_P1);
  float* P2   = (float*)(smem + SM_P2);
  float* P3   = (float*)(smem + SM_P3);
  float* S1   = (float*)(smem + SM_S1);
  float* S2   = (float*)(smem + SM_S2);

  const int tid = threadIdx.x;
  const int kt  = (tid >> 4) & 1;               // K-half (lane bit 4)
  const int rp  = (tid >> 1) & 7;               // row pair: rows 2rp, 2rp+1
  const int q   = ((tid >> 5) << 1) | (tid & 1);// colgroup 0..15 (2 per warp)
  const int row = 2 * rp + kt;                  // LN-phase row ownership
  const int n0  = blockIdx.x * NROWS;

  // Stage W [192][256] into SMEM
  {
    const float4* s4 = (const float4*)Wg;
    float4* d4 = (float4*)Wsh;
    for (int i = tid; i < 192 * 256 / 4; i += 256) d4[i] = s4[i];
  }
  for (int i = tid; i < NROWS * HP; i += 256) hbuf[i] = 0.f;   // h0 = 0

  load_x_async(obss, acts, xbuf, n0, 0, tid);
  asm volatile("cp.async.commit_group;");

  // Loop-invariant constants
  float gam[5][4], bet[5][4], dwr[4];
#pragma unroll
  for (int g = 0; g < 5; g++) {
    float4 gv = *(const float4*)(gamma + g * 64 + 4 * q);
    float4 bv = *(const float4*)(beta  + g * 64 + 4 * q);
    gam[g][0] = gv.x; gam[g][1] = gv.y; gam[g][2] = gv.z; gam[g][3] = gv.w;
    bet[g][0] = bv.x; bet[g][1] = bv.y; bet[g][2] = bv.z; bet[g][3] = bv.w;
  }
  {
    float4 dv = *(const float4*)(dW + 4 * q);
    dwr[0] = dv.x; dwr[1] = dv.y; dwr[2] = dv.z; dwr[3] = dv.w;
  }
  const float dbr = db[0];

  // K-segment offsets for this thread's K-half:
  //   segA: 32 k from xbuf at col (kt?96:0),  W rows (kt?96:0)
  //   segB: 64 k from (kt ? hbuf : xbuf+32),  W rows (kt?128:32)
  const int  koffA = kt ? 96 : 0;
  const float* wA  = Wsh + (size_t)koffA * 256 + 4 * q;
  const float* wB  = Wsh + (size_t)(kt ? 128 : 32) * 256 + 4 * q;
  const float* hB0 = hbuf + (2 * rp) * HP;      // used when kt==1
  const float* hB1 = hbuf + (2 * rp + 1) * HP;

  float cstate[4] = {0.f, 0.f, 0.f, 0.f};       // carried post-LN c for (row, 4q..4q+3)

  asm volatile("cp.async.wait_group 0;");
  __syncthreads();

  for (int t = 0; t < TSTEPS; t++) {
    const int cur = t & 1;
    if (t + 1 < TSTEPS) load_x_async(obss, acts, xbuf + (cur ^ 1) * NROWS * XP, n0, t + 1, tid);
    asm volatile("cp.async.commit_group;");

    // ---- GEMM: acc[row0/row1][16 cols as 8 f32x2], K split across lane bit 4 ----
    unsigned long long acc0[8], acc1[8];
#pragma unroll
    for (int i = 0; i < 8; i++) { acc0[i] = 0ull; acc1[i] = 0ull; }

    const float* xc  = xbuf + cur * NROWS * XP;
    const float* pA0 = xc + (2 * rp) * XP + koffA;
    const float* pA1 = xc + (2 * rp + 1) * XP + koffA;
    const float* pB0 = kt ? hB0 : (xc + (2 * rp) * XP + 32);
    const float* pB1 = kt ? hB1 : (xc + (2 * rp + 1) * XP + 32);

    gemm_seg<32>(pA0, pA1, wA, acc0, acc1);
    gemm_seg<64>(pB0, pB1, wB, acc0, acc1);

    // ---- in-warp split-K combine (xor lane bit 4), no smem, no syncs ----
#pragma unroll
    for (int i = 0; i < 8; i++) {
      unsigned long long o0 = __shfl_xor_sync(0xffffffffu, acc0[i], 16);
      ADD2(acc0[i], o0);
      unsigned long long o1 = __shfl_xor_sync(0xffffffffu, acc1[i], 16);
      ADD2(acc1[i], o1);
    }

    // This thread proceeds with row = 2rp+kt
    float z[4][4];
#pragma unroll
    for (int g = 0; g < 4; g++) {
      unsigned long long za = kt ? acc1[2 * g]     : acc0[2 * g];
      unsigned long long zb = kt ? acc1[2 * g + 1] : acc0[2 * g + 1];
      float2 a = unpack2(za);
      float2 b = unpack2(zb);
      z[g][0] = a.x; z[g][1] = a.y; z[g][2] = b.x; z[g][3] = b.y;
    }

    // ---- Gate layernorm stats (per row, per gate, over 64 = 16 q-threads x 4) ----
#pragma unroll
    for (int g = 0; g < 4; g++) {
      float s  = z[g][0] + z[g][1] + z[g][2] + z[g][3];
      float ss = z[g][0] * z[g][0] + z[g][1] * z[g][1] + z[g][2] * z[g][2] + z[g][3] * z[g][3];
      ((float2*)P1)[(row * 16 + q) * 4 + g] = make_float2(s, ss);
    }
    __syncthreads();
    if (tid < 64) {                       // thread -> (gate g, row rr)
      const int g  = tid >> 4;
      const int rr = tid & 15;
      float s = 0.f, ss = 0.f;
#pragma unroll
      for (int qq = 0; qq < 16; qq++) {
        float2 p = ((const float2*)P1)[(rr * 16 + qq) * 4 + g];
        s += p.x; ss += p.y;
      }
      float m = s * 0.015625f;
      float v = fmaxf(ss * 0.015625f - m * m, 0.f);
      ((float2*)S1)[rr * 4 + g] = make_float2(m, rsqrtf(v + 1e-12f));
    }
    __syncthreads();

    // ---- Normalize gates, LSTM cell ----
    float2 sti = ((const float2*)S1)[row * 4 + 0];
    float2 stj = ((const float2*)S1)[row * 4 + 1];
    float2 stf = ((const float2*)S1)[row * 4 + 2];
    float2 sto = ((const float2*)S1)[row * 4 + 3];
    float nc[4], on[4];
    float cs = 0.f, css = 0.f;
#pragma unroll
    for (int j = 0; j < 4; j++) {
      float zi = (z[0][j] - sti.x) * sti.y * gam[0][j] + bet[0][j];
      float zj = (z[1][j] - stj.x) * stj.y * gam[1][j] + bet[1][j];
      float zf = (z[2][j] - stf.x) * stf.y * gam[2][j] + bet[2][j];
      on[j]    = (z[3][j] - sto.x) * sto.y * gam[3][j] + bet[3][j];
      float c = cstate[j] * sigm(zf + 1.f) + sigm(zi) * tanhx(zj);   // forget_bias = 1
      nc[j] = c; cs += c; css += c * c;
    }
    ((float2*)P2)[row * 16 + q] = make_float2(cs, css);
    __syncthreads();
    if (tid < 16) {                        // thread -> row rr, reduce c-LN stats
      const int rr = tid;
      const float2* b2 = (const float2*)P2 + rr * 16;
      float s = 0.f, ss = 0.f;
#pragma unroll
      for (int qq = 0; qq < 16; qq++) { float2 p = b2[qq]; s += p.x; ss += p.y; }
      float m = s * 0.015625f;
      float v = fmaxf(ss * 0.015625f - m * m, 0.f);
      ((float2*)S2)[rr] = make_float2(m, rsqrtf(v + 1e-12f));
    }
    __syncthreads();

    // ---- c-LN, new h, per-thread q-partial ----
    float2 stc = ((const float2*)S2)[row];
    float qp = 0.f;
    float hv[4];
#pragma unroll
    for (int j = 0; j < 4; j++) {
      float cn = (nc[j] - stc.x) * stc.y * gam[4][j] + bet[4][j];
      cstate[j] = cn;                                   // carried c is post-LN
      float h = tanhx(cn) * sigm(on[j]);
      hv[j] = h;
      qp += h * dwr[j];
    }
    *(float4*)(hbuf + row * HP + 4 * q) = make_float4(hv[0], hv[1], hv[2], hv[3]);
    P3[row * 16 + q] = qp;
    asm volatile("cp.async.wait_group 0;");             // x_{t+1} staged
    __syncthreads();                                    // h + x visible for next step
    if (tid < 16) {
      const int rr = tid;
      const float* b3 = P3 + rr * 16;
      float s = dbr;
#pragma unroll
      for (int qq = 0; qq < 16; qq++) s += b3[qq];
      out[(size_t)(n0 + rr) * TSTEPS + t] = s;          // q[n][t]
    }
  }
}

extern "C" void kernel_launch(void* const* d_in, const int* in_sizes, int n_in,
                              void* d_out, int out_size) {
  const float* obss  = (const float*)d_in[0];
  const float* acts  = (const float*)d_in[1];
  const float* W     = (const float*)d_in[2];
  const float* gamma = (const float*)d_in[3];
  const float* beta  = (const float*)d_in[4];
  const float* dW    = (const float*)d_in[5];
  const float* db    = (const float*)d_in[6];
  float* out = (float*)d_out;

  cudaFuncSetAttribute(critic_lnlstm_kernel,
                       cudaFuncAttributeMaxDynamicSharedMemorySize, SM_TOTAL);
  critic_lnlstm_kernel<<<128, 256, SM_TOTAL>>>(obss, acts, W, gamma, beta, dW, db, out);
}

// round 9
// speedup vs baseline: 1.5993x; 1.1398x over previous
#include <cuda_runtime.h>
#include <cuda_bf16.h>
#include <cstdint>

#define TSTEPS 256
#define NROWS  16

__device__ float zx_buf[134217728];   // [2048*256 rows][256 cols] fp32 scratch (512 MB)

// ---------- helpers ----------
__device__ __forceinline__ unsigned long long pack2(float x, float y) {
  unsigned long long r; asm("mov.b64 %0, {%1, %2};" : "=l"(r) : "f"(x), "f"(y)); return r;
}
__device__ __forceinline__ float2 unpack2(unsigned long long v) {
  float2 f; asm("mov.b64 {%0, %1}, %2;" : "=f"(f.x), "=f"(f.y) : "l"(v)); return f;
}
#define FMA2(d, a, b) asm("fma.rn.f32x2 %0, %1, %2, %0;" : "+l"(d) : "l"(a), "l"(b))
#define ADD2(d, s)    asm("add.rn.f32x2 %0, %0, %1;" : "+l"(d) : "l"(s))
__device__ __forceinline__ float sigm(float x) { return __fdividef(1.f, 1.f + __expf(-x)); }
__device__ __forceinline__ float tanhx(float x) {
  float xx = fminf(fmaxf(x, -15.f), 15.f);
  float e = __expf(2.f * xx);
  return __fdividef(e - 1.f, e + 1.f);
}
__device__ __forceinline__ uint32_t smem_u32(const void* p) {
  return (uint32_t)__cvta_generic_to_shared(p);
}
__device__ __forceinline__ uint32_t split_pack(float a, float b, uint32_t& lo) {
  __nv_bfloat16 ha = __float2bfloat16(a), hb = __float2bfloat16(b);
  __nv_bfloat16 la = __float2bfloat16(a - __bfloat162float(ha));
  __nv_bfloat16 lb = __float2bfloat16(b - __bfloat162float(hb));
  lo = (uint32_t)__bfloat16_as_ushort(la) | ((uint32_t)__bfloat16_as_ushort(lb) << 16);
  return (uint32_t)__bfloat16_as_ushort(ha) | ((uint32_t)__bfloat16_as_ushort(hb) << 16);
}
#define LDM4(r0, r1, r2, r3, addr) \
  asm volatile("ldmatrix.sync.aligned.m8n8.x4.shared.b16 {%0,%1,%2,%3}, [%4];" \
               : "=r"(r0), "=r"(r1), "=r"(r2), "=r"(r3) : "r"(addr))
#define MMA16816(c, a, b0, b1) \
  asm volatile("mma.sync.aligned.m16n8k16.row.col.f32.bf16.bf16.f32 " \
               "{%0,%1,%2,%3}, {%4,%5,%6,%7}, {%8,%9}, {%0,%1,%2,%3};" \
               : "+f"((c)[0]), "+f"((c)[1]), "+f"((c)[2]), "+f"((c)[3]) \
               : "r"((a)[0]), "r"((a)[1]), "r"((a)[2]), "r"((a)[3]), "r"(b0), "r"(b1))

// ============ Kernel 1: zx = X @ Wx via mma.sync bf16 3-pass split ============
// Persistent, 148 CTAs x 256 threads (8 warps, 4(m) x 2(n)).
// Block tile M=128, N=256 (full), K=128; warp tile 32 x 128.
// A [128 m][128 k] bf16 hi/lo, pitch 136 bf16; B = Wx^T [256 n][128 k] hi/lo, pitch 136.

#define APITCH 136
#define BPITCH 136
#define K1_AHI   0
#define K1_ALO   34816
#define K1_BHI   69632
#define K1_BLO   139264
#define K1_TOTAL 208896

__global__ void __launch_bounds__(256, 1)
zx_gemm_kernel(const float* __restrict__ obss, const float* __restrict__ acts,
               const float* __restrict__ Wg) {
  extern __shared__ char sm[];
  const int tid = threadIdx.x, lane = tid & 31, warp = tid >> 5;
  const int warp_m = warp & 3, warp_n = warp >> 2;
  const uint32_t sb = smem_u32(sm);

  // ---- convert B = Wx^T once: thread = n (0..255), all 128 k ----
  {
    const int n = tid;
#pragma unroll 4
    for (int k = 0; k < 128; k += 2) {
      float w0 = Wg[(size_t)k * 256 + n];
      float w1 = Wg[(size_t)(k + 1) * 256 + n];
      uint32_t lo, hi = split_pack(w0, w1, lo);
      uint32_t bo = (uint32_t)(n * BPITCH + k) * 2;
      *(uint32_t*)(sm + K1_BHI + bo) = hi;
      *(uint32_t*)(sm + K1_BLO + bo) = lo;
    }
  }

  // ldmatrix per-lane byte offsets
  const uint32_t laneA = ((uint32_t)(lane & 15) * APITCH + (uint32_t)(lane >> 4) * 8) * 2;
  const uint32_t laneB = (((uint32_t)(lane & 7) + (uint32_t)((lane >> 4) << 3)) * BPITCH +
                          (uint32_t)((lane >> 3) & 1) * 8) * 2;
  const int arow = tid >> 1, ahalf = tid & 1;    // A staging: 2 threads/row, 64 cols each
  const int er = lane >> 2, ec = (lane & 3) * 2; // epilogue frag coords

  for (int tile = blockIdx.x; tile < 4096; tile += gridDim.x) {
    const int m0 = tile * 128;
    {   // stage + split-convert A rows
      const int m = m0 + arow, nn = m >> 8, tt = m & 255;
      const float* so = obss + ((size_t)nn * 256 + tt) * 96;
      const float* sa = acts + ((size_t)nn * 256 + tt) * 32;
#pragma unroll
      for (int i = 0; i < 16; i++) {
        int c = ahalf * 64 + 4 * i;
        float4 v = (c < 96) ? *(const float4*)(so + c) : *(const float4*)(sa + (c - 96));
        uint32_t lo0, hi0 = split_pack(v.x, v.y, lo0);
        uint32_t lo1, hi1 = split_pack(v.z, v.w, lo1);
        uint32_t bo = (uint32_t)(arow * APITCH + c) * 2;
        *(uint32_t*)(sm + K1_AHI + bo)     = hi0;
        *(uint32_t*)(sm + K1_AHI + bo + 4) = hi1;
        *(uint32_t*)(sm + K1_ALO + bo)     = lo0;
        *(uint32_t*)(sm + K1_ALO + bo + 4) = lo1;
      }
    }
    __syncthreads();

    float acc[2][16][4];
#pragma unroll
    for (int mt = 0; mt < 2; mt++)
#pragma unroll
      for (int nt = 0; nt < 16; nt++)
#pragma unroll
        for (int j = 0; j < 4; j++) acc[mt][nt][j] = 0.f;

    for (int p = 0; p < 3; p++) {   // AhiBhi, AhiBlo, AloBhi
      uint32_t abase = sb + ((p < 2) ? K1_AHI : K1_ALO) +
                       (uint32_t)(warp_m * 32) * APITCH * 2 + laneA;
      uint32_t bbase = sb + ((p == 1) ? K1_BLO : K1_BHI) +
                       (uint32_t)(warp_n * 128) * BPITCH * 2 + laneB;
#pragma unroll
      for (int ks = 0; ks < 8; ks++) {
        uint32_t a[2][4];
        LDM4(a[0][0], a[0][1], a[0][2], a[0][3], abase + ks * 32);
        LDM4(a[1][0], a[1][1], a[1][2], a[1][3], abase + 16 * APITCH * 2 + ks * 32);
#pragma unroll
        for (int nt2 = 0; nt2 < 8; nt2++) {
          uint32_t b0, b1, b2, b3;
          LDM4(b0, b1, b2, b3, bbase + (uint32_t)(nt2 * 16) * BPITCH * 2 + ks * 32);
          MMA16816(acc[0][2 * nt2],     a[0], b0, b1);
          MMA16816(acc[0][2 * nt2 + 1], a[0], b2, b3);
          MMA16816(acc[1][2 * nt2],     a[1], b0, b1);
          MMA16816(acc[1][2 * nt2 + 1], a[1], b2, b3);
        }
      }
    }

    // epilogue: D frag c0,c1 -> (row, col..col+1); c2,c3 -> (row+8, ...)
#pragma unroll
    for (int mt = 0; mt < 2; mt++) {
#pragma unroll
      for (int nt = 0; nt < 16; nt++) {
        int row = m0 + warp_m * 32 + mt * 16 + er;
        int col = warp_n * 128 + nt * 8 + ec;
        *(float2*)(zx_buf + (size_t)row * 256 + col)       = make_float2(acc[mt][nt][0], acc[mt][nt][1]);
        *(float2*)(zx_buf + (size_t)(row + 8) * 256 + col) = make_float2(acc[mt][nt][2], acc[mt][nt][3]);
      }
    }
    __syncthreads();
  }
}

// ============ Kernel 2: recurrent LN-LSTM, K=64 (h @ Wh) + streamed zx ============
#define HP   68
#define ZXP  264
#define WP   264   // Wh row pitch (floats); rows k>=32 additionally rotated +8 floats

#define SM2_W     0                              // 64*264*4 = 67584
#define SM2_ZX    67584                          // 2*16*264*4 = 33792
#define SM2_HBUF  (SM2_ZX + 2*NROWS*ZXP*4)       // +4352
#define SM2_P1    (SM2_HBUF + NROWS*HP*4)        // +8192
#define SM2_P2    (SM2_P1 + NROWS*16*8*4)        // +2048
#define SM2_P3    (SM2_P2 + NROWS*16*2*4)        // +1024
#define SM2_S1    (SM2_P3 + NROWS*16*4)          // +512
#define SM2_S2    (SM2_S1 + NROWS*4*2*4)         // +128
#define SM2_TOTAL (SM2_S2 + NROWS*2*4)           // 117,632 B

__device__ __forceinline__ void load_zx_async(float* dst, int n0, int t, int tid) {
#pragma unroll
  for (int it = 0; it < 4; it++) {
    int idx = tid + it * 256;
    int row = idx >> 6, cc = idx & 63;
    const float* src = zx_buf + ((size_t)(n0 + row) * 256 + t) * 256 + cc * 4;
    uint32_t da = smem_u32(dst + row * ZXP + cc * 4);
    asm volatile("cp.async.ca.shared.global [%0], [%1], 16;" :: "r"(da), "l"(src));
  }
}

__global__ void __launch_bounds__(256, 1)
critic_recur_kernel(const float* __restrict__ Wg,   const float* __restrict__ gamma,
                    const float* __restrict__ beta, const float* __restrict__ dW,
                    const float* __restrict__ db,   float* __restrict__ out) {
  extern __shared__ char smem[];
  float* Wsh  = (float*)(smem + SM2_W);
  float* zxs  = (float*)(smem + SM2_ZX);
  float* hbuf = (float*)(smem + SM2_HBUF);
  float* P1   = (float*)(smem + SM2_P1);
  float* P2   = (float*)(smem + SM2_P2);
  float* P3   = (float*)(smem + SM2_P3);
  float* S1   = (float*)(smem + SM2_S1);
  float* S2   = (float*)(smem + SM2_S2);

  const int tid = threadIdx.x;
  const int kt  = (tid >> 4) & 1;                 // K-half of 64 (lane bit 4)
  const int rp  = (tid >> 1) & 7;                 // row pair
  const int q   = ((tid >> 5) << 1) | (tid & 1);  // colgroup 0..15 (2 per warp)
  const int row = 2 * rp + kt;
  const int n0  = blockIdx.x * NROWS;

  // Stage Wh = Wg rows 128..191; pitch 264, +8-float rotation for k>=32 (bank-group fix)
  for (int i = tid; i < 64 * 256; i += 256) {
    int k = i >> 8, c = i & 255;
    Wsh[k * WP + ((k >= 32) ? 8 : 0) + c] = Wg[(size_t)(128 + k) * 256 + c];
  }
  for (int i = tid; i < NROWS * HP; i += 256) hbuf[i] = 0.f;

  load_zx_async(zxs, n0, 0, tid);
  asm volatile("cp.async.commit_group;");

  float gam[5][4], bet[5][4], dwr[4];
#pragma unroll
  for (int g = 0; g < 5; g++) {
    float4 gv = *(const float4*)(gamma + g * 64 + 4 * q);
    float4 bv = *(const float4*)(beta  + g * 64 + 4 * q);
    gam[g][0]=gv.x; gam[g][1]=gv.y; gam[g][2]=gv.z; gam[g][3]=gv.w;
    bet[g][0]=bv.x; bet[g][1]=bv.y; bet[g][2]=bv.z; bet[g][3]=bv.w;
  }
  { float4 dv = *(const float4*)(dW + 4 * q); dwr[0]=dv.x; dwr[1]=dv.y; dwr[2]=dv.z; dwr[3]=dv.w; }
  const float dbr = db[0];

  const float* wB  = Wsh + (size_t)kt * (32 * WP + 8) + 4 * q;
  const float* hB0 = hbuf + (2 * rp) * HP + kt * 32;
  const float* hB1 = hbuf + (2 * rp + 1) * HP + kt * 32;

  float cstate[4] = {0.f, 0.f, 0.f, 0.f};
  asm volatile("cp.async.wait_group 0;");
  __syncthreads();

  for (int t = 0; t < TSTEPS; t++) {
    const int cur = t & 1;
    if (t + 1 < TSTEPS) load_zx_async(zxs + (cur ^ 1) * NROWS * ZXP, n0, t + 1, tid);
    asm volatile("cp.async.commit_group;");

    // ---- h @ Wh: 2 rows x 16 cols, 32 k per K-half ----
    unsigned long long acc0[8], acc1[8];
#pragma unroll
    for (int i = 0; i < 8; i++) { acc0[i] = 0ull; acc1[i] = 0ull; }
#pragma unroll 2
    for (int k = 0; k < 32; k += 4) {
      float4 a4 = *(const float4*)(hB0 + k);
      float4 b4 = *(const float4*)(hB1 + k);
      float xa[4] = {a4.x, a4.y, a4.z, a4.w};
      float xb[4] = {b4.x, b4.y, b4.z, b4.w};
#pragma unroll
      for (int kk = 0; kk < 4; kk++) {
        unsigned long long ua = pack2(xa[kk], xa[kk]);
        unsigned long long ub = pack2(xb[kk], xb[kk]);
        const float* wr = wB + (k + kk) * WP;
#pragma unroll
        for (int g = 0; g < 4; g++) {
          ulonglong2 wv = *(const ulonglong2*)(wr + g * 64);
          FMA2(acc0[2*g],   ua, wv.x);  FMA2(acc0[2*g+1], ua, wv.y);
          FMA2(acc1[2*g],   ub, wv.x);  FMA2(acc1[2*g+1], ub, wv.y);
        }
      }
    }
#pragma unroll
    for (int i = 0; i < 8; i++) {
      unsigned long long o0 = __shfl_xor_sync(0xffffffffu, acc0[i], 16); ADD2(acc0[i], o0);
      unsigned long long o1 = __shfl_xor_sync(0xffffffffu, acc1[i], 16); ADD2(acc1[i], o1);
    }

    // owner thread (row = 2rp+kt): z = zx + h@Wh
    float z[4][4];
    const float* zrow = zxs + cur * NROWS * ZXP + row * ZXP;
#pragma unroll
    for (int g = 0; g < 4; g++) {
      float2 a = unpack2(kt ? acc1[2*g]   : acc0[2*g]);
      float2 b = unpack2(kt ? acc1[2*g+1] : acc0[2*g+1]);
      float4 zx4 = *(const float4*)(zrow + g * 64 + 4 * q);
      z[g][0] = a.x + zx4.x; z[g][1] = a.y + zx4.y;
      z[g][2] = b.x + zx4.z; z[g][3] = b.y + zx4.w;
    }

    // ---- gate LN stats ----
#pragma unroll
    for (int g = 0; g < 4; g++) {
      float s  = z[g][0] + z[g][1] + z[g][2] + z[g][3];
      float ss = z[g][0]*z[g][0] + z[g][1]*z[g][1] + z[g][2]*z[g][2] + z[g][3]*z[g][3];
      ((float2*)P1)[(row * 16 + q) * 4 + g] = make_float2(s, ss);
    }
    __syncthreads();
    if (tid < 64) {
      const int g = tid >> 4, rr = tid & 15;
      float s = 0.f, ss = 0.f;
#pragma unroll
      for (int qq = 0; qq < 16; qq++) {
        float2 p = ((const float2*)P1)[(rr * 16 + qq) * 4 + g];
        s += p.x; ss += p.y;
      }
      float m = s * 0.015625f;
      float v = fmaxf(ss * 0.015625f - m * m, 0.f);
      ((float2*)S1)[rr * 4 + g] = make_float2(m, rsqrtf(v + 1e-12f));
    }
    __syncthreads();

    // ---- normalize, cell ----
    float2 sti = ((const float2*)S1)[row*4+0], stj = ((const float2*)S1)[row*4+1];
    float2 stf = ((const float2*)S1)[row*4+2], sto = ((const float2*)S1)[row*4+3];
    float nc[4], on[4]; float cs = 0.f, css = 0.f;
#pragma unroll
    for (int j = 0; j < 4; j++) {
      float zi = (z[0][j]-sti.x)*sti.y*gam[0][j]+bet[0][j];
      float zj = (z[1][j]-stj.x)*stj.y*gam[1][j]+bet[1][j];
      float zf = (z[2][j]-stf.x)*stf.y*gam[2][j]+bet[2][j];
      on[j]    = (z[3][j]-sto.x)*sto.y*gam[3][j]+bet[3][j];
      float c = cstate[j]*sigm(zf+1.f) + sigm(zi)*tanhx(zj);
      nc[j] = c; cs += c; css += c*c;
    }
    ((float2*)P2)[row * 16 + q] = make_float2(cs, css);
    __syncthreads();
    if (tid < 16) {
      const float2* b2 = (const float2*)P2 + tid * 16;
      float s = 0.f, ss = 0.f;
#pragma unroll
      for (int qq = 0; qq < 16; qq++) { float2 p = b2[qq]; s += p.x; ss += p.y; }
      float m = s * 0.015625f;
      float v = fmaxf(ss * 0.015625f - m * m, 0.f);
      ((float2*)S2)[tid] = make_float2(m, rsqrtf(v + 1e-12f));
    }
    __syncthreads();

    // ---- c-LN, h, dense partial ----
    float2 stc = ((const float2*)S2)[row];
    float qp = 0.f; float hv[4];
#pragma unroll
    for (int j = 0; j < 4; j++) {
      float cn = (nc[j]-stc.x)*stc.y*gam[4][j]+bet[4][j];
      cstate[j] = cn;
      float h = tanhx(cn) * sigm(on[j]);
      hv[j] = h; qp += h * dwr[j];
    }
    *(float4*)(hbuf + row * HP + 4 * q) = make_float4(hv[0], hv[1], hv[2], hv[3]);
    P3[row * 16 + q] = qp;
    asm volatile("cp.async.wait_group 0;");
    __syncthreads();
    if (tid < 16) {
      const float* b3 = P3 + tid * 16;
      float s = dbr;
#pragma unroll
      for (int qq = 0; qq < 16; qq++) s += b3[qq];
      out[(size_t)(n0 + tid) * TSTEPS + t] = s;
    }
  }
}

extern "C" void kernel_launch(void* const* d_in, const int* in_sizes, int n_in,
                              void* d_out, int out_size) {
  const float* obss  = (const float*)d_in[0];
  const float* acts  = (const float*)d_in[1];
  const float* W     = (const float*)d_in[2];
  const float* gamma = (const float*)d_in[3];
  const float* beta  = (const float*)d_in[4];
  const float* dW    = (const float*)d_in[5];
  const float* db    = (const float*)d_in[6];
  float* out = (float*)d_out;

  cudaFuncSetAttribute(zx_gemm_kernel, cudaFuncAttributeMaxDynamicSharedMemorySize, K1_TOTAL);
  cudaFuncSetAttribute(critic_recur_kernel, cudaFuncAttributeMaxDynamicSharedMemorySize, SM2_TOTAL);
  zx_gemm_kernel<<<148, 256, K1_TOTAL>>>(obss, acts, W);
  critic_recur_kernel<<<128, 256, SM2_TOTAL>>>(W, gamma, beta, dW, db, out);
}

// round 11
// speedup vs baseline: 1.6219x; 1.0141x over previous
#include <cuda_runtime.h>
#include <cuda_bf16.h>
#include <cstdint>

#define TSTEPS 256
#define NROWS  16

__device__ float zx_buf[134217728];   // [2048*256 rows][256 cols] fp32 scratch (512 MB)

// ---------- helpers ----------
__device__ __forceinline__ unsigned long long pack2(float x, float y) {
  unsigned long long r; asm("mov.b64 %0, {%1, %2};" : "=l"(r) : "f"(x), "f"(y)); return r;
}
__device__ __forceinline__ float2 unpack2(unsigned long long v) {
  float2 f; asm("mov.b64 {%0, %1}, %2;" : "=f"(f.x), "=f"(f.y) : "l"(v)); return f;
}
#define FMA2(d, a, b) asm("fma.rn.f32x2 %0, %1, %2, %0;" : "+l"(d) : "l"(a), "l"(b))
#define ADD2(d, s)    asm("add.rn.f32x2 %0, %0, %1;" : "+l"(d) : "l"(s))
__device__ __forceinline__ float sigm(float x) { return __fdividef(1.f, 1.f + __expf(-x)); }
__device__ __forceinline__ float tanhx(float x) {
  float xx = fminf(fmaxf(x, -15.f), 15.f);
  float e = __expf(2.f * xx);
  return __fdividef(e - 1.f, e + 1.f);
}
__device__ __forceinline__ uint32_t smem_u32(const void* p) {
  return (uint32_t)__cvta_generic_to_shared(p);
}
__device__ __forceinline__ uint32_t split_pack(float a, float b, uint32_t& lo) {
  __nv_bfloat16 ha = __float2bfloat16(a), hb = __float2bfloat16(b);
  __nv_bfloat16 la = __float2bfloat16(a - __bfloat162float(ha));
  __nv_bfloat16 lb = __float2bfloat16(b - __bfloat162float(hb));
  lo = (uint32_t)__bfloat16_as_ushort(la) | ((uint32_t)__bfloat16_as_ushort(lb) << 16);
  return (uint32_t)__bfloat16_as_ushort(ha) | ((uint32_t)__bfloat16_as_ushort(hb) << 16);
}
#define LDM4(r0, r1, r2, r3, addr) \
  asm volatile("ldmatrix.sync.aligned.m8n8.x4.shared.b16 {%0,%1,%2,%3}, [%4];" \
               : "=r"(r0), "=r"(r1), "=r"(r2), "=r"(r3) : "r"(addr))
#define MMA16816(c, a, b0, b1) \
  asm volatile("mma.sync.aligned.m16n8k16.row.col.f32.bf16.bf16.f32 " \
               "{%0,%1,%2,%3}, {%4,%5,%6,%7}, {%8,%9}, {%0,%1,%2,%3};" \
               : "+f"((c)[0]), "+f"((c)[1]), "+f"((c)[2]), "+f"((c)[3]) \
               : "r"((a)[0]), "r"((a)[1]), "r"((a)[2]), "r"((a)[3]), "r"(b0), "r"(b1))

// ============ Kernel 1: zx = X @ Wx via mma.sync bf16 3-pass split ============
// Persistent, 148 CTAs x 256 threads (8 warps, 4(m) x 2(n)).
// Coalesced epilogue: D staged through the A smem region in two 64-row halves.

#define APITCH 136
#define BPITCH 136
#define K1_AHI   0
#define K1_ALO   34816
#define K1_BHI   69632
#define K1_BLO   139264
#define K1_TOTAL 208896

__global__ void __launch_bounds__(256, 1)
zx_gemm_kernel(const float* __restrict__ obss, const float* __restrict__ acts,
               const float* __restrict__ Wg) {
  extern __shared__ char sm[];
  const int tid = threadIdx.x, lane = tid & 31, warp = tid >> 5;
  const int warp_m = warp & 3, warp_n = warp >> 2;
  const uint32_t sb = smem_u32(sm);

  // ---- convert B = Wx^T once: thread = n (0..255), all 128 k ----
  {
    const int n = tid;
#pragma unroll 4
    for (int k = 0; k < 128; k += 2) {
      float w0 = Wg[(size_t)k * 256 + n];
      float w1 = Wg[(size_t)(k + 1) * 256 + n];
      uint32_t lo, hi = split_pack(w0, w1, lo);
      uint32_t bo = (uint32_t)(n * BPITCH + k) * 2;
      *(uint32_t*)(sm + K1_BHI + bo) = hi;
      *(uint32_t*)(sm + K1_BLO + bo) = lo;
    }
  }

  const uint32_t laneA = ((uint32_t)(lane & 15) * APITCH + (uint32_t)(lane >> 4) * 8) * 2;
  const uint32_t laneB = (((uint32_t)(lane & 7) + (uint32_t)((lane >> 4) << 3)) * BPITCH +
                          (uint32_t)((lane >> 3) & 1) * 8) * 2;
  const int arow = tid >> 1, ahalf = tid & 1;    // A staging: 2 threads/row, 64 cols each
  const int er = lane >> 2, ec = (lane & 3) * 2; // frag coords

  for (int tile = blockIdx.x; tile < 4096; tile += gridDim.x) {
    const int m0 = tile * 128;
    {   // stage + split-convert A rows
      const int m = m0 + arow, nn = m >> 8, tt = m & 255;
      const float* so = obss + ((size_t)nn * 256 + tt) * 96;
      const float* sa = acts + ((size_t)nn * 256 + tt) * 32;
#pragma unroll
      for (int i = 0; i < 16; i++) {
        int c = ahalf * 64 + 4 * i;
        float4 v = (c < 96) ? *(const float4*)(so + c) : *(const float4*)(sa + (c - 96));
        uint32_t lo0, hi0 = split_pack(v.x, v.y, lo0);
        uint32_t lo1, hi1 = split_pack(v.z, v.w, lo1);
        uint32_t bo = (uint32_t)(arow * APITCH + c) * 2;
        *(uint32_t*)(sm + K1_AHI + bo)     = hi0;
        *(uint32_t*)(sm + K1_AHI + bo + 4) = hi1;
        *(uint32_t*)(sm + K1_ALO + bo)     = lo0;
        *(uint32_t*)(sm + K1_ALO + bo + 4) = lo1;
      }
    }
    __syncthreads();

    float acc[2][16][4];
#pragma unroll
    for (int mt = 0; mt < 2; mt++)
#pragma unroll
      for (int nt = 0; nt < 16; nt++)
#pragma unroll
        for (int j = 0; j < 4; j++) acc[mt][nt][j] = 0.f;

    for (int p = 0; p < 3; p++) {   // AhiBhi, AhiBlo, AloBhi
      uint32_t abase = sb + ((p < 2) ? K1_AHI : K1_ALO) +
                       (uint32_t)(warp_m * 32) * APITCH * 2 + laneA;
      uint32_t bbase = sb + ((p == 1) ? K1_BLO : K1_BHI) +
                       (uint32_t)(warp_n * 128) * BPITCH * 2 + laneB;
#pragma unroll
      for (int ks = 0; ks < 8; ks++) {
        uint32_t a[2][4];
        LDM4(a[0][0], a[0][1], a[0][2], a[0][3], abase + ks * 32);
        LDM4(a[1][0], a[1][1], a[1][2], a[1][3], abase + 16 * APITCH * 2 + ks * 32);
#pragma unroll
        for (int nt2 = 0; nt2 < 8; nt2++) {
          uint32_t b0, b1, b2, b3;
          LDM4(b0, b1, b2, b3, bbase + (uint32_t)(nt2 * 16) * BPITCH * 2 + ks * 32);
          MMA16816(acc[0][2 * nt2],     a[0], b0, b1);
          MMA16816(acc[0][2 * nt2 + 1], a[0], b2, b3);
          MMA16816(acc[1][2 * nt2],     a[1], b0, b1);
          MMA16816(acc[1][2 * nt2 + 1], a[1], b2, b3);
        }
      }
    }

    // ---- coalesced epilogue via smem (reuse A hi+lo region: 64 rows x 256 cols fp32) ----
    float* Dsm = (float*)(sm + K1_AHI);
#pragma unroll
    for (int half = 0; half < 2; half++) {
      __syncthreads();                      // A/Dsm region free
      if ((warp_m >> 1) == half) {
#pragma unroll
        for (int mt = 0; mt < 2; mt++)
#pragma unroll
          for (int nt = 0; nt < 16; nt++) {
            int lrow = warp_m * 32 + mt * 16 + er - half * 64;
            int col  = warp_n * 128 + nt * 8 + ec;
            *(float2*)(Dsm + lrow * 256 + col)       = make_float2(acc[mt][nt][0], acc[mt][nt][1]);
            *(float2*)(Dsm + (lrow + 8) * 256 + col) = make_float2(acc[mt][nt][2], acc[mt][nt][3]);
          }
      }
      __syncthreads();
      const float4* Ds4 = (const float4*)Dsm;
      float* gbase = zx_buf + (size_t)(m0 + half * 64) * 256;
#pragma unroll
      for (int j = 0; j < 16; j++) {
        int f = j * 256 + tid;              // float4 index: lanes contiguous
        float4 v = Ds4[f];
        *(float4*)(gbase + f * 4) = v;
      }
    }
    __syncthreads();                        // Dsm reads done before next A staging
  }
}

// ============ Kernel 2: recurrent LN-LSTM, K=64, warp-local LN via shfl ============
#define HP   68
#define ZXP  264
#define WP   264   // Wh row pitch (floats); rows k>=32 additionally rotated +8 floats
#define ZP   264   // z transpose buffer pitch

#define SM2_W     0                              // 64*264*4 = 67584
#define SM2_ZX    67584                          // 2*16*264*4 = 33792
#define SM2_HBUF  (SM2_ZX + 2*NROWS*ZXP*4)       // +4352
#define SM2_Z     (SM2_HBUF + NROWS*HP*4)        // +16896
#define SM2_TOTAL (SM2_Z + NROWS*ZP*4)           // 122,624 B

__device__ __forceinline__ void load_zx_async(float* dst, int n0, int t, int tid) {
#pragma unroll
  for (int it = 0; it < 4; it++) {
    int idx = tid + it * 256;
    int row = idx >> 6, cc = idx & 63;
    const float* src = zx_buf + ((size_t)(n0 + row) * 256 + t) * 256 + cc * 4;
    uint32_t da = smem_u32(dst + row * ZXP + cc * 4);
    asm volatile("cp.async.ca.shared.global [%0], [%1], 16;" :: "r"(da), "l"(src));
  }
}

__global__ void __launch_bounds__(256, 1)
critic_recur_kernel(const float* __restrict__ Wg,   const float* __restrict__ gamma,
                    const float* __restrict__ beta, const float* __restrict__ dW,
                    const float* __restrict__ db,   float* __restrict__ out) {
  extern __shared__ char smem[];
  float* Wsh  = (float*)(smem + SM2_W);
  float* zxs  = (float*)(smem + SM2_ZX);
  float* hbuf = (float*)(smem + SM2_HBUF);
  float* Z    = (float*)(smem + SM2_Z);

  const int tid = threadIdx.x;
  // GEMM mapping (broadcast-friendly W reads)
  const int kt  = (tid >> 4) & 1;                 // K-half (lane bit 4)
  const int rp  = (tid >> 1) & 7;                 // row pair
  const int q   = ((tid >> 5) << 1) | (tid & 1);  // colgroup 0..15
  const int row = 2 * rp + kt;                    // GEMM owner row
  // LN mapping (warp-local rows)
  const int lane = tid & 31, wrp = tid >> 5;
  const int rowB = 2 * wrp + (lane >> 4);         // warp owns 2 rows
  const int qb   = lane & 15;                     // colgroup within row
  const int n0  = blockIdx.x * NROWS;

  // Stage Wh = Wg rows 128..191; pitch 264, +8-float rotation for k>=32
  for (int i = tid; i < 64 * 256; i += 256) {
    int k = i >> 8, c = i & 255;
    Wsh[k * WP + ((k >= 32) ? 8 : 0) + c] = Wg[(size_t)(128 + k) * 256 + c];
  }
  for (int i = tid; i < NROWS * HP; i += 256) hbuf[i] = 0.f;

  load_zx_async(zxs, n0, 0, tid);
  asm volatile("cp.async.commit_group;");

  // LN-phase constants indexed by qb
  float gam[5][4], bet[5][4], dwr[4];
#pragma unroll
  for (int g = 0; g < 5; g++) {
    float4 gv = *(const float4*)(gamma + g * 64 + 4 * qb);
    float4 bv = *(const float4*)(beta  + g * 64 + 4 * qb);
    gam[g][0]=gv.x; gam[g][1]=gv.y; gam[g][2]=gv.z; gam[g][3]=gv.w;
    bet[g][0]=bv.x; bet[g][1]=bv.y; bet[g][2]=bv.z; bet[g][3]=bv.w;
  }
  { float4 dv = *(const float4*)(dW + 4 * qb); dwr[0]=dv.x; dwr[1]=dv.y; dwr[2]=dv.z; dwr[3]=dv.w; }
  const float dbr = db[0];

  const float* wB  = Wsh + (size_t)kt * (32 * WP + 8) + 4 * q;
  const float* hB0 = hbuf + (2 * rp) * HP + kt * 32;
  const float* hB1 = hbuf + (2 * rp + 1) * HP + kt * 32;

  float cstate[4] = {0.f, 0.f, 0.f, 0.f};   // carried post-LN c for (rowB, 4qb..4qb+3)
  asm volatile("cp.async.wait_group 0;");
  __syncthreads();

  for (int t = 0; t < TSTEPS; t++) {
    const int cur = t & 1;
    if (t + 1 < TSTEPS) load_zx_async(zxs + (cur ^ 1) * NROWS * ZXP, n0, t + 1, tid);
    asm volatile("cp.async.commit_group;");

    // ---- h @ Wh: 2 rows x 16 cols, 32 k per K-half ----
    unsigned long long acc0[8], acc1[8];
#pragma unroll
    for (int i = 0; i < 8; i++) { acc0[i] = 0ull; acc1[i] = 0ull; }
#pragma unroll 2
    for (int k = 0; k < 32; k += 4) {
      float4 a4 = *(const float4*)(hB0 + k);
      float4 b4 = *(const float4*)(hB1 + k);
      float xa[4] = {a4.x, a4.y, a4.z, a4.w};
      float xb[4] = {b4.x, b4.y, b4.z, b4.w};
#pragma unroll
      for (int kk = 0; kk < 4; kk++) {
        unsigned long long ua = pack2(xa[kk], xa[kk]);
        unsigned long long ub = pack2(xb[kk], xb[kk]);
        const float* wr = wB + (k + kk) * WP;
#pragma unroll
        for (int g = 0; g < 4; g++) {
          ulonglong2 wv = *(const ulonglong2*)(wr + g * 64);
          FMA2(acc0[2*g],   ua, wv.x);  FMA2(acc0[2*g+1], ua, wv.y);
          FMA2(acc1[2*g],   ub, wv.x);  FMA2(acc1[2*g+1], ub, wv.y);
        }
      }
    }
#pragma unroll
    for (int i = 0; i < 8; i++) {
      unsigned long long o0 = __shfl_xor_sync(0xffffffffu, acc0[i], 16); ADD2(acc0[i], o0);
      unsigned long long o1 = __shfl_xor_sync(0xffffffffu, acc1[i], 16); ADD2(acc1[i], o1);
    }

    // owner (row = 2rp+kt) writes h@Wh to Z transpose buffer
    {
      float* Zr = Z + row * ZP;
#pragma unroll
      for (int g = 0; g < 4; g++) {
        float2 a = unpack2(kt ? acc1[2*g]   : acc0[2*g]);
        float2 b = unpack2(kt ? acc1[2*g+1] : acc0[2*g+1]);
        *(float4*)(Zr + g * 64 + 4 * q) = make_float4(a.x, a.y, b.x, b.y);
      }
    }
    __syncthreads();

    // ---- LN phase: warp-local rows, all reductions via 16-lane shfl ----
    const float* zr  = Z + rowB * ZP;
    const float* zxr = zxs + cur * NROWS * ZXP + rowB * ZXP;
    float z[4][4];
    float2 st[4];
#pragma unroll
    for (int g = 0; g < 4; g++) {
      float4 a = *(const float4*)(zr  + g * 64 + 4 * qb);
      float4 b = *(const float4*)(zxr + g * 64 + 4 * qb);
      z[g][0] = a.x + b.x; z[g][1] = a.y + b.y; z[g][2] = a.z + b.z; z[g][3] = a.w + b.w;
      float s  = z[g][0] + z[g][1] + z[g][2] + z[g][3];
      float ss = z[g][0]*z[g][0] + z[g][1]*z[g][1] + z[g][2]*z[g][2] + z[g][3]*z[g][3];
      unsigned long long p = pack2(s, ss);
#pragma unroll
      for (int m = 8; m >= 1; m >>= 1) {
        unsigned long long o = __shfl_xor_sync(0xffffffffu, p, m); ADD2(p, o);
      }
      float2 sv = unpack2(p);
      float mu = sv.x * 0.015625f;
      float var = fmaxf(sv.y * 0.015625f - mu * mu, 0.f);
      st[g] = make_float2(mu, rsqrtf(var + 1e-12f));
    }

    float nc[4], on[4]; float cs = 0.f, css = 0.f;
#pragma unroll
    for (int j = 0; j < 4; j++) {
      float zi = (z[0][j]-st[0].x)*st[0].y*gam[0][j]+bet[0][j];
      float zj = (z[1][j]-st[1].x)*st[1].y*gam[1][j]+bet[1][j];
      float zf = (z[2][j]-st[2].x)*st[2].y*gam[2][j]+bet[2][j];
      on[j]    = (z[3][j]-st[3].x)*st[3].y*gam[3][j]+bet[3][j];
      float c = cstate[j]*sigm(zf+1.f) + sigm(zi)*tanhx(zj);   // forget_bias = 1
      nc[j] = c; cs += c; css += c*c;
    }
    {
      unsigned long long p = pack2(cs, css);
#pragma unroll
      for (int m = 8; m >= 1; m >>= 1) {
        unsigned long long o = __shfl_xor_sync(0xffffffffu, p, m); ADD2(p, o);
      }
      float2 sv = unpack2(p);
      float mu = sv.x * 0.015625f;
      float var = fmaxf(sv.y * 0.015625f - mu * mu, 0.f);
      float rstd = rsqrtf(var + 1e-12f);
      float qp = 0.f; float hv[4];
#pragma unroll
      for (int j = 0; j < 4; j++) {
        float cn = (nc[j]-mu)*rstd*gam[4][j]+bet[4][j];
        cstate[j] = cn;
        float h = tanhx(cn) * sigm(on[j]);
        hv[j] = h; qp += h * dwr[j];
      }
      *(float4*)(hbuf + rowB * HP + 4 * qb) = make_float4(hv[0], hv[1], hv[2], hv[3]);
#pragma unroll
      for (int m = 8; m >= 1; m >>= 1) qp += __shfl_xor_sync(0xffffffffu, qp, m);
      if (qb == 0) out[(size_t)(n0 + rowB) * TSTEPS + t] = dbr + qp;
    }

    asm volatile("cp.async.wait_group 0;");   // x_{t+1}'s zx staged
    __syncthreads();                          // h + zx visible for next step
  }
}

extern "C" void kernel_launch(void* const* d_in, const int* in_sizes, int n_in,
                              void* d_out, int out_size) {
  const float* obss  = (const float*)d_in[0];
  const float* acts  = (const float*)d_in[1];
  const float* W     = (const float*)d_in[2];
  const float* gamma = (const float*)d_in[3];
  const float* beta  = (const float*)d_in[4];
  const float* dW    = (const float*)d_in[5];
  const float* db    = (const float*)d_in[6];
  float* out = (float*)d_out;

  cudaFuncSetAttribute(zx_gemm_kernel, cudaFuncAttributeMaxDynamicSharedMemorySize, K1_TOTAL);
  cudaFuncSetAttribute(critic_recur_kernel, cudaFuncAttributeMaxDynamicSharedMemorySize, SM2_TOTAL);
  zx_gemm_kernel<<<148, 256, K1_TOTAL>>>(obss, acts, W);
  critic_recur_kernel<<<128, 256, SM2_TOTAL>>>(W, gamma, beta, dW, db, out);
}

// round 12
// speedup vs baseline: 1.8710x; 1.1536x over previous
#include <cuda_runtime.h>
#include <cuda_bf16.h>
#include <cstdint>

#define TSTEPS 256
#define NROWS  16

__device__ float zx_buf[134217728];   // [2048*256 rows][256 cols] fp32 scratch (512 MB)

// ---------- helpers ----------
__device__ __forceinline__ unsigned long long pack2(float x, float y) {
  unsigned long long r; asm("mov.b64 %0, {%1, %2};" : "=l"(r) : "f"(x), "f"(y)); return r;
}
__device__ __forceinline__ float2 unpack2(unsigned long long v) {
  float2 f; asm("mov.b64 {%0, %1}, %2;" : "=f"(f.x), "=f"(f.y) : "l"(v)); return f;
}
#define FMA2(d, a, b) asm("fma.rn.f32x2 %0, %1, %2, %0;" : "+l"(d) : "l"(a), "l"(b))
#define ADD2(d, s)    asm("add.rn.f32x2 %0, %0, %1;" : "+l"(d) : "l"(s))
__device__ __forceinline__ float sigm(float x) { return __fdividef(1.f, 1.f + __expf(-x)); }
__device__ __forceinline__ float tanhx(float x) {
  float xx = fminf(fmaxf(x, -15.f), 15.f);
  float e = __expf(2.f * xx);
  return __fdividef(e - 1.f, e + 1.f);
}
__device__ __forceinline__ uint32_t smem_u32(const void* p) {
  return (uint32_t)__cvta_generic_to_shared(p);
}
__device__ __forceinline__ uint32_t split_pack(float a, float b, uint32_t& lo) {
  __nv_bfloat16 ha = __float2bfloat16(a), hb = __float2bfloat16(b);
  __nv_bfloat16 la = __float2bfloat16(a - __bfloat162float(ha));
  __nv_bfloat16 lb = __float2bfloat16(b - __bfloat162float(hb));
  lo = (uint32_t)__bfloat16_as_ushort(la) | ((uint32_t)__bfloat16_as_ushort(lb) << 16);
  return (uint32_t)__bfloat16_as_ushort(ha) | ((uint32_t)__bfloat16_as_ushort(hb) << 16);
}
#define LDM4(r0, r1, r2, r3, addr) \
  asm volatile("ldmatrix.sync.aligned.m8n8.x4.shared.b16 {%0,%1,%2,%3}, [%4];" \
               : "=r"(r0), "=r"(r1), "=r"(r2), "=r"(r3) : "r"(addr))
#define MMA16816(c, a, b0, b1) \
  asm volatile("mma.sync.aligned.m16n8k16.row.col.f32.bf16.bf16.f32 " \
               "{%0,%1,%2,%3}, {%4,%5,%6,%7}, {%8,%9}, {%0,%1,%2,%3};" \
               : "+f"((c)[0]), "+f"((c)[1]), "+f"((c)[2]), "+f"((c)[3]) \
               : "r"((a)[0]), "r"((a)[1]), "r"((a)[2]), "r"((a)[3]), "r"(b0), "r"(b1))

// ============ Kernel 1: zx = X @ Wx via mma.sync bf16 3-pass split ============
// Persistent, 148 CTAs x 256 threads (8 warps, 4(m) x 2(n)).
// Direct-store epilogue (R9-measured best): dense tile => L2 merges sectors, no staging.

#define APITCH 136
#define BPITCH 136
#define K1_AHI   0
#define K1_ALO   34816
#define K1_BHI   69632
#define K1_BLO   139264
#define K1_TOTAL 208896

__global__ void __launch_bounds__(256, 1)
zx_gemm_kernel(const float* __restrict__ obss, const float* __restrict__ acts,
               const float* __restrict__ Wg) {
  extern __shared__ char sm[];
  const int tid = threadIdx.x, lane = tid & 31, warp = tid >> 5;
  const int warp_m = warp & 3, warp_n = warp >> 2;
  const uint32_t sb = smem_u32(sm);

  // ---- convert B = Wx^T once: thread = n (0..255), all 128 k ----
  {
    const int n = tid;
#pragma unroll 4
    for (int k = 0; k < 128; k += 2) {
      float w0 = Wg[(size_t)k * 256 + n];
      float w1 = Wg[(size_t)(k + 1) * 256 + n];
      uint32_t lo, hi = split_pack(w0, w1, lo);
      uint32_t bo = (uint32_t)(n * BPITCH + k) * 2;
      *(uint32_t*)(sm + K1_BHI + bo) = hi;
      *(uint32_t*)(sm + K1_BLO + bo) = lo;
    }
  }

  const uint32_t laneA = ((uint32_t)(lane & 15) * APITCH + (uint32_t)(lane >> 4) * 8) * 2;
  const uint32_t laneB = (((uint32_t)(lane & 7) + (uint32_t)((lane >> 4) << 3)) * BPITCH +
                          (uint32_t)((lane >> 3) & 1) * 8) * 2;
  const int arow = tid >> 1, ahalf = tid & 1;    // A staging: 2 threads/row, 64 cols each
  const int er = lane >> 2, ec = (lane & 3) * 2; // frag coords

  for (int tile = blockIdx.x; tile < 4096; tile += gridDim.x) {
    const int m0 = tile * 128;
    {   // stage + split-convert A rows
      const int m = m0 + arow, nn = m >> 8, tt = m & 255;
      const float* so = obss + ((size_t)nn * 256 + tt) * 96;
      const float* sa = acts + ((size_t)nn * 256 + tt) * 32;
#pragma unroll
      for (int i = 0; i < 16; i++) {
        int c = ahalf * 64 + 4 * i;
        float4 v = (c < 96) ? *(const float4*)(so + c) : *(const float4*)(sa + (c - 96));
        uint32_t lo0, hi0 = split_pack(v.x, v.y, lo0);
        uint32_t lo1, hi1 = split_pack(v.z, v.w, lo1);
        uint32_t bo = (uint32_t)(arow * APITCH + c) * 2;
        *(uint32_t*)(sm + K1_AHI + bo)     = hi0;
        *(uint32_t*)(sm + K1_AHI + bo + 4) = hi1;
        *(uint32_t*)(sm + K1_ALO + bo)     = lo0;
        *(uint32_t*)(sm + K1_ALO + bo + 4) = lo1;
      }
    }
    __syncthreads();

    float acc[2][16][4];
#pragma unroll
    for (int mt = 0; mt < 2; mt++)
#pragma unroll
      for (int nt = 0; nt < 16; nt++)
#pragma unroll
        for (int j = 0; j < 4; j++) acc[mt][nt][j] = 0.f;

    for (int p = 0; p < 3; p++) {   // AhiBhi, AhiBlo, AloBhi
      uint32_t abase = sb + ((p < 2) ? K1_AHI : K1_ALO) +
                       (uint32_t)(warp_m * 32) * APITCH * 2 + laneA;
      uint32_t bbase = sb + ((p == 1) ? K1_BLO : K1_BHI) +
                       (uint32_t)(warp_n * 128) * BPITCH * 2 + laneB;
#pragma unroll
      for (int ks = 0; ks < 8; ks++) {
        uint32_t a[2][4];
        LDM4(a[0][0], a[0][1], a[0][2], a[0][3], abase + ks * 32);
        LDM4(a[1][0], a[1][1], a[1][2], a[1][3], abase + 16 * APITCH * 2 + ks * 32);
#pragma unroll
        for (int nt2 = 0; nt2 < 8; nt2++) {
          uint32_t b0, b1, b2, b3;
          LDM4(b0, b1, b2, b3, bbase + (uint32_t)(nt2 * 16) * BPITCH * 2 + ks * 32);
          MMA16816(acc[0][2 * nt2],     a[0], b0, b1);
          MMA16816(acc[0][2 * nt2 + 1], a[0], b2, b3);
          MMA16816(acc[1][2 * nt2],     a[1], b0, b1);
          MMA16816(acc[1][2 * nt2 + 1], a[1], b2, b3);
        }
      }
    }

    // direct epilogue: dense tile writes, L2 merges sectors (R9-measured best)
#pragma unroll
    for (int mt = 0; mt < 2; mt++) {
#pragma unroll
      for (int nt = 0; nt < 16; nt++) {
        int row = m0 + warp_m * 32 + mt * 16 + er;
        int col = warp_n * 128 + nt * 8 + ec;
        *(float2*)(zx_buf + (size_t)row * 256 + col)       = make_float2(acc[mt][nt][0], acc[mt][nt][1]);
        *(float2*)(zx_buf + (size_t)(row + 8) * 256 + col) = make_float2(acc[mt][nt][2], acc[mt][nt][3]);
      }
    }
    __syncthreads();
  }
}

// ============ Kernel 2: recurrent LN-LSTM, K=64, warp-local LN via shfl ============
#define HP   68
#define ZXP  264
#define WP   264   // Wh row pitch (floats); rows k>=32 additionally rotated +8 floats
#define ZP   264   // z transpose buffer pitch

#define SM2_W     0                              // 64*264*4 = 67584
#define SM2_ZX    67584                          // 2*16*264*4 = 33792
#define SM2_HBUF  (SM2_ZX + 2*NROWS*ZXP*4)       // +4352
#define SM2_Z     (SM2_HBUF + NROWS*HP*4)        // +16896
#define SM2_TOTAL (SM2_Z + NROWS*ZP*4)           // 122,624 B

__device__ __forceinline__ void load_zx_async(float* dst, int n0, int t, int tid) {
#pragma unroll
  for (int it = 0; it < 4; it++) {
    int idx = tid + it * 256;
    int row = idx >> 6, cc = idx & 63;
    const float* src = zx_buf + ((size_t)(n0 + row) * 256 + t) * 256 + cc * 4;
    uint32_t da = smem_u32(dst + row * ZXP + cc * 4);
    asm volatile("cp.async.ca.shared.global [%0], [%1], 16;" :: "r"(da), "l"(src));
  }
}

__global__ void __launch_bounds__(256, 1)
critic_recur_kernel(const float* __restrict__ Wg,   const float* __restrict__ gamma,
                    const float* __restrict__ beta, const float* __restrict__ dW,
                    const float* __restrict__ db,   float* __restrict__ out) {
  extern __shared__ char smem[];
  float* Wsh  = (float*)(smem + SM2_W);
  float* zxs  = (float*)(smem + SM2_ZX);
  float* hbuf = (float*)(smem + SM2_HBUF);
  float* Z    = (float*)(smem + SM2_Z);

  const int tid = threadIdx.x;
  // GEMM mapping (broadcast-friendly W reads)
  const int kt  = (tid >> 4) & 1;                 // K-half (lane bit 4)
  const int rp  = (tid >> 1) & 7;                 // row pair
  const int q   = ((tid >> 5) << 1) | (tid & 1);  // colgroup 0..15
  const int row = 2 * rp + kt;                    // GEMM owner row
  // LN mapping (warp-local rows)
  const int lane = tid & 31, wrp = tid >> 5;
  const int rowB = 2 * wrp + (lane >> 4);         // warp owns 2 rows
  const int qb   = lane & 15;                     // colgroup within row
  const int n0  = blockIdx.x * NROWS;

  // Stage Wh = Wg rows 128..191; pitch 264, +8-float rotation for k>=32
  for (int i = tid; i < 64 * 256; i += 256) {
    int k = i >> 8, c = i & 255;
    Wsh[k * WP + ((k >= 32) ? 8 : 0) + c] = Wg[(size_t)(128 + k) * 256 + c];
  }
  for (int i = tid; i < NROWS * HP; i += 256) hbuf[i] = 0.f;

  load_zx_async(zxs, n0, 0, tid);
  asm volatile("cp.async.commit_group;");

  // LN-phase constants indexed by qb
  float gam[5][4], bet[5][4], dwr[4];
#pragma unroll
  for (int g = 0; g < 5; g++) {
    float4 gv = *(const float4*)(gamma + g * 64 + 4 * qb);
    float4 bv = *(const float4*)(beta  + g * 64 + 4 * qb);
    gam[g][0]=gv.x; gam[g][1]=gv.y; gam[g][2]=gv.z; gam[g][3]=gv.w;
    bet[g][0]=bv.x; bet[g][1]=bv.y; bet[g][2]=bv.z; bet[g][3]=bv.w;
  }
  { float4 dv = *(const float4*)(dW + 4 * qb); dwr[0]=dv.x; dwr[1]=dv.y; dwr[2]=dv.z; dwr[3]=dv.w; }
  const float dbr = db[0];

  const float* wB  = Wsh + (size_t)kt * (32 * WP + 8) + 4 * q;
  const float* hB0 = hbuf + (2 * rp) * HP + kt * 32;
  const float* hB1 = hbuf + (2 * rp + 1) * HP + kt * 32;

  float cstate[4] = {0.f, 0.f, 0.f, 0.f};   // carried post-LN c for (rowB, 4qb..4qb+3)
  asm volatile("cp.async.wait_group 0;");
  __syncthreads();

  for (int t = 0; t < TSTEPS; t++) {
    const int cur = t & 1;
    if (t + 1 < TSTEPS) load_zx_async(zxs + (cur ^ 1) * NROWS * ZXP, n0, t + 1, tid);
    asm volatile("cp.async.commit_group;");

    // ---- h @ Wh: 2 rows x 16 cols, 32 k per K-half ----
    unsigned long long acc0[8], acc1[8];
#pragma unroll
    for (int i = 0; i < 8; i++) { acc0[i] = 0ull; acc1[i] = 0ull; }
#pragma unroll 2
    for (int k = 0; k < 32; k += 4) {
      float4 a4 = *(const float4*)(hB0 + k);
      float4 b4 = *(const float4*)(hB1 + k);
      float xa[4] = {a4.x, a4.y, a4.z, a4.w};
      float xb[4] = {b4.x, b4.y, b4.z, b4.w};
#pragma unroll
      for (int kk = 0; kk < 4; kk++) {
        unsigned long long ua = pack2(xa[kk], xa[kk]);
        unsigned long long ub = pack2(xb[kk], xb[kk]);
        const float* wr = wB + (k + kk) * WP;
#pragma unroll
        for (int g = 0; g < 4; g++) {
          ulonglong2 wv = *(const ulonglong2*)(wr + g * 64);
          FMA2(acc0[2*g],   ua, wv.x);  FMA2(acc0[2*g+1], ua, wv.y);
          FMA2(acc1[2*g],   ub, wv.x);  FMA2(acc1[2*g+1], ub, wv.y);
        }
      }
    }
#pragma unroll
    for (int i = 0; i < 8; i++) {
      unsigned long long o0 = __shfl_xor_sync(0xffffffffu, acc0[i], 16); ADD2(acc0[i], o0);
      unsigned long long o1 = __shfl_xor_sync(0xffffffffu, acc1[i], 16); ADD2(acc1[i], o1);
    }

    // owner (row = 2rp+kt) writes h@Wh to Z transpose buffer
    {
      float* Zr = Z + row * ZP;
#pragma unroll
      for (int g = 0; g < 4; g++) {
        float2 a = unpack2(kt ? acc1[2*g]   : acc0[2*g]);
        float2 b = unpack2(kt ? acc1[2*g+1] : acc0[2*g+1]);
        *(float4*)(Zr + g * 64 + 4 * q) = make_float4(a.x, a.y, b.x, b.y);
      }
    }
    __syncthreads();

    // ---- LN phase: warp-local rows, all reductions via 16-lane shfl ----
    const float* zr  = Z + rowB * ZP;
    const float* zxr = zxs + cur * NROWS * ZXP + rowB * ZXP;
    float z[4][4];
    float2 st[4];
#pragma unroll
    for (int g = 0; g < 4; g++) {
      float4 a = *(const float4*)(zr  + g * 64 + 4 * qb);
      float4 b = *(const float4*)(zxr + g * 64 + 4 * qb);
      z[g][0] = a.x + b.x; z[g][1] = a.y + b.y; z[g][2] = a.z + b.z; z[g][3] = a.w + b.w;
      float s  = z[g][0] + z[g][1] + z[g][2] + z[g][3];
      float ss = z[g][0]*z[g][0] + z[g][1]*z[g][1] + z[g][2]*z[g][2] + z[g][3]*z[g][3];
      unsigned long long p = pack2(s, ss);
#pragma unroll
      for (int m = 8; m >= 1; m >>= 1) {
        unsigned long long o = __shfl_xor_sync(0xffffffffu, p, m); ADD2(p, o);
      }
      float2 sv = unpack2(p);
      float mu = sv.x * 0.015625f;
      float var = fmaxf(sv.y * 0.015625f - mu * mu, 0.f);
      st[g] = make_float2(mu, rsqrtf(var + 1e-12f));
    }

    float nc[4], on[4]; float cs = 0.f, css = 0.f;
#pragma unroll
    for (int j = 0; j < 4; j++) {
      float zi = (z[0][j]-st[0].x)*st[0].y*gam[0][j]+bet[0][j];
      float zj = (z[1][j]-st[1].x)*st[1].y*gam[1][j]+bet[1][j];
      float zf = (z[2][j]-st[2].x)*st[2].y*gam[2][j]+bet[2][j];
      on[j]    = (z[3][j]-st[3].x)*st[3].y*gam[3][j]+bet[3][j];
      float c = cstate[j]*sigm(zf+1.f) + sigm(zi)*tanhx(zj);   // forget_bias = 1
      nc[j] = c; cs += c; css += c*c;
    }
    {
      unsigned long long p = pack2(cs, css);
#pragma unroll
      for (int m = 8; m >= 1; m >>= 1) {
        unsigned long long o = __shfl_xor_sync(0xffffffffu, p, m); ADD2(p, o);
      }
      float2 sv = unpack2(p);
      float mu = sv.x * 0.015625f;
      float var = fmaxf(sv.y * 0.015625f - mu * mu, 0.f);
      float rstd = rsqrtf(var + 1e-12f);
      float qp = 0.f; float hv[4];
#pragma unroll
      for (int j = 0; j < 4; j++) {
        float cn = (nc[j]-mu)*rstd*gam[4][j]+bet[4][j];
        cstate[j] = cn;
        float h = tanhx(cn) * sigm(on[j]);
        hv[j] = h; qp += h * dwr[j];
      }
      *(float4*)(hbuf + rowB * HP + 4 * qb) = make_float4(hv[0], hv[1], hv[2], hv[3]);
#pragma unroll
      for (int m = 8; m >= 1; m >>= 1) qp += __shfl_xor_sync(0xffffffffu, qp, m);
      if (qb == 0) out[(size_t)(n0 + rowB) * TSTEPS + t] = dbr + qp;
    }

    asm volatile("cp.async.wait_group 0;");   // x_{t+1}'s zx staged
    __syncthreads();                          // h + zx visible for next step
  }
}

extern "C" void kernel_launch(void* const* d_in, const int* in_sizes, int n_in,
                              void* d_out, int out_size) {
  const float* obss  = (const float*)d_in[0];
  const float* acts  = (const float*)d_in[1];
  const float* W     = (const float*)d_in[2];
  const float* gamma = (const float*)d_in[3];
  const float* beta  = (const float*)d_in[4];
  const float* dW    = (const float*)d_in[5];
  const float* db    = (const float*)d_in[6];
  float* out = (float*)d_out;

  cudaFuncSetAttribute(zx_gemm_kernel, cudaFuncAttributeMaxDynamicSharedMemorySize, K1_TOTAL);
  cudaFuncSetAttribute(critic_recur_kernel, cudaFuncAttributeMaxDynamicSharedMemorySize, SM2_TOTAL);
  zx_gemm_kernel<<<148, 256, K1_TOTAL>>>(obss, acts, W);
  critic_recur_kernel<<<128, 256, SM2_TOTAL>>>(W, gamma, beta, dW, db, out);
}

// round 13
// speedup vs baseline: 1.9084x; 1.0200x over previous
#include <cuda_runtime.h>
#include <cuda_bf16.h>
#include <cstdint>

#define TSTEPS 256

__device__ float zx_buf[134217728];   // [2048*256 rows][256 cols] fp32 scratch (512 MB)

// ---------- helpers ----------
__device__ __forceinline__ unsigned long long pack2(float x, float y) {
  unsigned long long r; asm("mov.b64 %0, {%1, %2};" : "=l"(r) : "f"(x), "f"(y)); return r;
}
__device__ __forceinline__ float2 unpack2(unsigned long long v) {
  float2 f; asm("mov.b64 {%0, %1}, %2;" : "=f"(f.x), "=f"(f.y) : "l"(v)); return f;
}
#define FMA2(d, a, b) asm("fma.rn.f32x2 %0, %1, %2, %0;" : "+l"(d) : "l"(a), "l"(b))
#define ADD2(d, s)    asm("add.rn.f32x2 %0, %0, %1;" : "+l"(d) : "l"(s))
__device__ __forceinline__ float sigm(float x) { return __fdividef(1.f, 1.f + __expf(-x)); }
__device__ __forceinline__ float tanhx(float x) {
  float xx = fminf(fmaxf(x, -15.f), 15.f);
  float e = __expf(2.f * xx);
  return __fdividef(e - 1.f, e + 1.f);
}
__device__ __forceinline__ uint32_t smem_u32(const void* p) {
  return (uint32_t)__cvta_generic_to_shared(p);
}
__device__ __forceinline__ uint32_t split_pack(float a, float b, uint32_t& lo) {
  __nv_bfloat16 ha = __float2bfloat16(a), hb = __float2bfloat16(b);
  __nv_bfloat16 la = __float2bfloat16(a - __bfloat162float(ha));
  __nv_bfloat16 lb = __float2bfloat16(b - __bfloat162float(hb));
  lo = (uint32_t)__bfloat16_as_ushort(la) | ((uint32_t)__bfloat16_as_ushort(lb) << 16);
  return (uint32_t)__bfloat16_as_ushort(ha) | ((uint32_t)__bfloat16_as_ushort(hb) << 16);
}
#define LDM4(r0, r1, r2, r3, addr) \
  asm volatile("ldmatrix.sync.aligned.m8n8.x4.shared.b16 {%0,%1,%2,%3}, [%4];" \
               : "=r"(r0), "=r"(r1), "=r"(r2), "=r"(r3) : "r"(addr))
#define MMA16816(c, a, b0, b1) \
  asm volatile("mma.sync.aligned.m16n8k16.row.col.f32.bf16.bf16.f32 " \
               "{%0,%1,%2,%3}, {%4,%5,%6,%7}, {%8,%9}, {%0,%1,%2,%3};" \
               : "+f"((c)[0]), "+f"((c)[1]), "+f"((c)[2]), "+f"((c)[3]) \
               : "r"((a)[0]), "r"((a)[1]), "r"((a)[2]), "r"((a)[3]), "r"(b0), "r"(b1))

// ============ Kernel 1: zx = X @ Wx via mma.sync bf16 3-pass split (unchanged) ============
#define APITCH 136
#define BPITCH 136
#define K1_AHI   0
#define K1_ALO   34816
#define K1_BHI   69632
#define K1_BLO   139264
#define K1_TOTAL 208896

__global__ void __launch_bounds__(256, 1)
zx_gemm_kernel(const float* __restrict__ obss, const float* __restrict__ acts,
               const float* __restrict__ Wg) {
  extern __shared__ char sm[];
  const int tid = threadIdx.x, lane = tid & 31, warp = tid >> 5;
  const int warp_m = warp & 3, warp_n = warp >> 2;
  const uint32_t sb = smem_u32(sm);

  {   // convert B = Wx^T once: thread = n (0..255), all 128 k
    const int n = tid;
#pragma unroll 4
    for (int k = 0; k < 128; k += 2) {
      float w0 = Wg[(size_t)k * 256 + n];
      float w1 = Wg[(size_t)(k + 1) * 256 + n];
      uint32_t lo, hi = split_pack(w0, w1, lo);
      uint32_t bo = (uint32_t)(n * BPITCH + k) * 2;
      *(uint32_t*)(sm + K1_BHI + bo) = hi;
      *(uint32_t*)(sm + K1_BLO + bo) = lo;
    }
  }

  const uint32_t laneA = ((uint32_t)(lane & 15) * APITCH + (uint32_t)(lane >> 4) * 8) * 2;
  const uint32_t laneB = (((uint32_t)(lane & 7) + (uint32_t)((lane >> 4) << 3)) * BPITCH +
                          (uint32_t)((lane >> 3) & 1) * 8) * 2;
  const int arow = tid >> 1, ahalf = tid & 1;
  const int er = lane >> 2, ec = (lane & 3) * 2;

  for (int tile = blockIdx.x; tile < 4096; tile += gridDim.x) {
    const int m0 = tile * 128;
    {   // stage + split-convert A rows
      const int m = m0 + arow, nn = m >> 8, tt = m & 255;
      const float* so = obss + ((size_t)nn * 256 + tt) * 96;
      const float* sa = acts + ((size_t)nn * 256 + tt) * 32;
#pragma unroll
      for (int i = 0; i < 16; i++) {
        int c = ahalf * 64 + 4 * i;
        float4 v = (c < 96) ? *(const float4*)(so + c) : *(const float4*)(sa + (c - 96));
        uint32_t lo0, hi0 = split_pack(v.x, v.y, lo0);
        uint32_t lo1, hi1 = split_pack(v.z, v.w, lo1);
        uint32_t bo = (uint32_t)(arow * APITCH + c) * 2;
        *(uint32_t*)(sm + K1_AHI + bo)     = hi0;
        *(uint32_t*)(sm + K1_AHI + bo + 4) = hi1;
        *(uint32_t*)(sm + K1_ALO + bo)     = lo0;
        *(uint32_t*)(sm + K1_ALO + bo + 4) = lo1;
      }
    }
    __syncthreads();

    float acc[2][16][4];
#pragma unroll
    for (int mt = 0; mt < 2; mt++)
#pragma unroll
      for (int nt = 0; nt < 16; nt++)
#pragma unroll
        for (int j = 0; j < 4; j++) acc[mt][nt][j] = 0.f;

    for (int p = 0; p < 3; p++) {   // AhiBhi, AhiBlo, AloBhi
      uint32_t abase = sb + ((p < 2) ? K1_AHI : K1_ALO) +
                       (uint32_t)(warp_m * 32) * APITCH * 2 + laneA;
      uint32_t bbase = sb + ((p == 1) ? K1_BLO : K1_BHI) +
                       (uint32_t)(warp_n * 128) * BPITCH * 2 + laneB;
#pragma unroll
      for (int ks = 0; ks < 8; ks++) {
        uint32_t a[2][4];
        LDM4(a[0][0], a[0][1], a[0][2], a[0][3], abase + ks * 32);
        LDM4(a[1][0], a[1][1], a[1][2], a[1][3], abase + 16 * APITCH * 2 + ks * 32);
#pragma unroll
        for (int nt2 = 0; nt2 < 8; nt2++) {
          uint32_t b0, b1, b2, b3;
          LDM4(b0, b1, b2, b3, bbase + (uint32_t)(nt2 * 16) * BPITCH * 2 + ks * 32);
          MMA16816(acc[0][2 * nt2],     a[0], b0, b1);
          MMA16816(acc[0][2 * nt2 + 1], a[0], b2, b3);
          MMA16816(acc[1][2 * nt2],     a[1], b0, b1);
          MMA16816(acc[1][2 * nt2 + 1], a[1], b2, b3);
        }
      }
    }

    // direct epilogue: dense tile writes, L2 merges sectors (measured best)
#pragma unroll
    for (int mt = 0; mt < 2; mt++) {
#pragma unroll
      for (int nt = 0; nt < 16; nt++) {
        int row = m0 + warp_m * 32 + mt * 16 + er;
        int col = warp_n * 128 + nt * 8 + ec;
        *(float2*)(zx_buf + (size_t)row * 256 + col)       = make_float2(acc[mt][nt][0], acc[mt][nt][1]);
        *(float2*)(zx_buf + (size_t)(row + 8) * 256 + col) = make_float2(acc[mt][nt][2], acc[mt][nt][3]);
      }
    }
    __syncthreads();
  }
}

// ============ Kernel 2: recurrent LN-LSTM, 256 CTAs x 128 thr, 2 CTAs/SM ============
#define NR2  8     // rows per CTA
#define HP   68
#define ZXP  264
#define WP   264   // Wh row pitch; rows k>=32 rotated +16 floats (bank-group disjoint)
#define ZP   264

#define SM2_W     0                              // (64*264+16)*4 = 67648
#define SM2_ZX    67648                          // 2*8*264*4 = 16896
#define SM2_HBUF  (SM2_ZX + 2*NR2*ZXP*4)         // +2176
#define SM2_Z     (SM2_HBUF + NR2*HP*4)          // +8448
#define SM2_TOTAL (SM2_Z + NR2*ZP*4)             // 95,168 B per CTA (x2/SM = 190,336)

__device__ __forceinline__ void load_zx_async(float* dst, int n0, int t, int tid) {
#pragma unroll
  for (int it = 0; it < 4; it++) {
    int idx = tid + it * 128;
    int row = idx >> 6, cc = idx & 63;        // 8 rows x 64 chunks
    const float* src = zx_buf + ((size_t)(n0 + row) * 256 + t) * 256 + cc * 4;
    uint32_t da = smem_u32(dst + row * ZXP + cc * 4);
    asm volatile("cp.async.ca.shared.global [%0], [%1], 16;" :: "r"(da), "l"(src));
  }
}

__global__ void __launch_bounds__(128, 2)
critic_recur_kernel(const float* __restrict__ Wg,   const float* __restrict__ gamma,
                    const float* __restrict__ beta, const float* __restrict__ dW,
                    const float* __restrict__ db,   float* __restrict__ out) {
  extern __shared__ char smem[];
  float* Wsh  = (float*)(smem + SM2_W);
  float* zxs  = (float*)(smem + SM2_ZX);
  float* hbuf = (float*)(smem + SM2_HBUF);
  float* Z    = (float*)(smem + SM2_Z);

  const int tid = threadIdx.x;
  // GEMM mapping: kt=b4, rp=b1-2, q = b6 b5 | b3 | b0  (bijective over 128)
  const int kt  = (tid >> 4) & 1;
  const int rp  = (tid >> 1) & 3;
  const int q   = ((tid >> 5) << 2) | (((tid >> 3) & 1) << 1) | (tid & 1);
  const int row = 2 * rp + kt;                  // GEMM owner row 0..7
  // LN mapping: 4 warps x 2 rows
  const int lane = tid & 31, wrp = tid >> 5;
  const int rowB = 2 * wrp + (lane >> 4);
  const int qb   = lane & 15;
  const int n0  = blockIdx.x * NR2;

  // Stage Wh = Wg rows 128..191; pitch 264, +16-float rotation for k>=32
  for (int i = tid; i < 64 * 256; i += 128) {
    int k = i >> 8, c = i & 255;
    Wsh[k * WP + ((k >= 32) ? 16 : 0) + c] = Wg[(size_t)(128 + k) * 256 + c];
  }
  for (int i = tid; i < NR2 * HP; i += 128) hbuf[i] = 0.f;

  load_zx_async(zxs, n0, 0, tid);
  asm volatile("cp.async.commit_group;");

  // LN-phase constants indexed by qb
  float gam[5][4], bet[5][4], dwr[4];
#pragma unroll
  for (int g = 0; g < 5; g++) {
    float4 gv = *(const float4*)(gamma + g * 64 + 4 * qb);
    float4 bv = *(const float4*)(beta  + g * 64 + 4 * qb);
    gam[g][0]=gv.x; gam[g][1]=gv.y; gam[g][2]=gv.z; gam[g][3]=gv.w;
    bet[g][0]=bv.x; bet[g][1]=bv.y; bet[g][2]=bv.z; bet[g][3]=bv.w;
  }
  { float4 dv = *(const float4*)(dW + 4 * qb); dwr[0]=dv.x; dwr[1]=dv.y; dwr[2]=dv.z; dwr[3]=dv.w; }
  const float dbr = db[0];

  const float* wB  = Wsh + (size_t)kt * (32 * WP + 16) + 4 * q;
  const float* hB0 = hbuf + (2 * rp) * HP + kt * 32;
  const float* hB1 = hbuf + (2 * rp + 1) * HP + kt * 32;

  float cstate[4] = {0.f, 0.f, 0.f, 0.f};   // carried post-LN c for (rowB, 4qb..4qb+3)
  asm volatile("cp.async.wait_group 0;");
  __syncthreads();

  for (int t = 0; t < TSTEPS; t++) {
    const int cur = t & 1;
    if (t + 1 < TSTEPS) load_zx_async(zxs + (cur ^ 1) * NR2 * ZXP, n0, t + 1, tid);
    asm volatile("cp.async.commit_group;");

    // ---- h @ Wh: 2 rows x 16 cols, 32 k per K-half ----
    unsigned long long acc0[8], acc1[8];
#pragma unroll
    for (int i = 0; i < 8; i++) { acc0[i] = 0ull; acc1[i] = 0ull; }
#pragma unroll 2
    for (int k = 0; k < 32; k += 4) {
      float4 a4 = *(const float4*)(hB0 + k);
      float4 b4 = *(const float4*)(hB1 + k);
      float xa[4] = {a4.x, a4.y, a4.z, a4.w};
      float xb[4] = {b4.x, b4.y, b4.z, b4.w};
#pragma unroll
      for (int kk = 0; kk < 4; kk++) {
        unsigned long long ua = pack2(xa[kk], xa[kk]);
        unsigned long long ub = pack2(xb[kk], xb[kk]);
        const float* wr = wB + (k + kk) * WP;
#pragma unroll
        for (int g = 0; g < 4; g++) {
          ulonglong2 wv = *(const ulonglong2*)(wr + g * 64);
          FMA2(acc0[2*g],   ua, wv.x);  FMA2(acc0[2*g+1], ua, wv.y);
          FMA2(acc1[2*g],   ub, wv.x);  FMA2(acc1[2*g+1], ub, wv.y);
        }
      }
    }
#pragma unroll
    for (int i = 0; i < 8; i++) {
      unsigned long long o0 = __shfl_xor_sync(0xffffffffu, acc0[i], 16); ADD2(acc0[i], o0);
      unsigned long long o1 = __shfl_xor_sync(0xffffffffu, acc1[i], 16); ADD2(acc1[i], o1);
    }

    // owner (row = 2rp+kt) writes h@Wh to Z transpose buffer
    {
      float* Zr = Z + row * ZP;
#pragma unroll
      for (int g = 0; g < 4; g++) {
        float2 a = unpack2(kt ? acc1[2*g]   : acc0[2*g]);
        float2 b = unpack2(kt ? acc1[2*g+1] : acc0[2*g+1]);
        *(float4*)(Zr + g * 64 + 4 * q) = make_float4(a.x, a.y, b.x, b.y);
      }
    }
    __syncthreads();

    // ---- LN phase: warp-local rows, 16-lane shfl reductions ----
    const float* zr  = Z + rowB * ZP;
    const float* zxr = zxs + cur * NR2 * ZXP + rowB * ZXP;
    float z[4][4];
    float2 st[4];
#pragma unroll
    for (int g = 0; g < 4; g++) {
      float4 a = *(const float4*)(zr  + g * 64 + 4 * qb);
      float4 b = *(const float4*)(zxr + g * 64 + 4 * qb);
      z[g][0] = a.x + b.x; z[g][1] = a.y + b.y; z[g][2] = a.z + b.z; z[g][3] = a.w + b.w;
      float s  = z[g][0] + z[g][1] + z[g][2] + z[g][3];
      float ss = z[g][0]*z[g][0] + z[g][1]*z[g][1] + z[g][2]*z[g][2] + z[g][3]*z[g][3];
      unsigned long long p = pack2(s, ss);
#pragma unroll
      for (int m = 8; m >= 1; m >>= 1) {
        unsigned long long o = __shfl_xor_sync(0xffffffffu, p, m); ADD2(p, o);
      }
      float2 sv = unpack2(p);
      float mu = sv.x * 0.015625f;
      float var = fmaxf(sv.y * 0.015625f - mu * mu, 0.f);
      st[g] = make_float2(mu, rsqrtf(var + 1e-12f));
    }

    float nc[4], on[4]; float cs = 0.f, css = 0.f;
#pragma unroll
    for (int j = 0; j < 4; j++) {
      float zi = (z[0][j]-st[0].x)*st[0].y*gam[0][j]+bet[0][j];
      float zj = (z[1][j]-st[1].x)*st[1].y*gam[1][j]+bet[1][j];
      float zf = (z[2][j]-st[2].x)*st[2].y*gam[2][j]+bet[2][j];
      on[j]    = (z[3][j]-st[3].x)*st[3].y*gam[3][j]+bet[3][j];
      float c = cstate[j]*sigm(zf+1.f) + sigm(zi)*tanhx(zj);   // forget_bias = 1
      nc[j] = c; cs += c; css += c*c;
    }
    {
      unsigned long long p = pack2(cs, css);
#pragma unroll
      for (int m = 8; m >= 1; m >>= 1) {
        unsigned long long o = __shfl_xor_sync(0xffffffffu, p, m); ADD2(p, o);
      }
      float2 sv = unpack2(p);
      float mu = sv.x * 0.015625f;
      float var = fmaxf(sv.y * 0.015625f - mu * mu, 0.f);
      float rstd = rsqrtf(var + 1e-12f);
      float qp = 0.f; float hv[4];
#pragma unroll
      for (int j = 0; j < 4; j++) {
        float cn = (nc[j]-mu)*rstd*gam[4][j]+bet[4][j];
        cstate[j] = cn;
        float h = tanhx(cn) * sigm(on[j]);
        hv[j] = h; qp += h * dwr[j];
      }
      *(float4*)(hbuf + rowB * HP + 4 * qb) = make_float4(hv[0], hv[1], hv[2], hv[3]);
#pragma unroll
      for (int m = 8; m >= 1; m >>= 1) qp += __shfl_xor_sync(0xffffffffu, qp, m);
      if (qb == 0) out[(size_t)(n0 + rowB) * TSTEPS + t] = dbr + qp;
    }

    asm volatile("cp.async.wait_group 0;");   // next zx staged
    __syncthreads();                          // h + zx visible for next step
  }
}

extern "C" void kernel_launch(void* const* d_in, const int* in_sizes, int n_in,
                              void* d_out, int out_size) {
  const float* obss  = (const float*)d_in[0];
  const float* acts  = (const float*)d_in[1];
  const float* W     = (const float*)d_in[2];
  const float* gamma = (const float*)d_in[3];
  const float* beta  = (const float*)d_in[4];
  const float* dW    = (const float*)d_in[5];
  const float* db    = (const float*)d_in[6];
  float* out = (float*)d_out;

  cudaFuncSetAttribute(zx_gemm_kernel, cudaFuncAttributeMaxDynamicSharedMemorySize, K1_TOTAL);
  cudaFuncSetAttribute(critic_recur_kernel, cudaFuncAttributeMaxDynamicSharedMemorySize, SM2_TOTAL);
  zx_gemm_kernel<<<148, 256, K1_TOTAL>>>(obss, acts, W);
  critic_recur_kernel<<<256, 128, SM2_TOTAL>>>(W, gamma, beta, dW, db, out);
}